// round 13
// baseline (speedup 1.0000x reference)
#include <cuda_runtime.h>
#include <cuda_fp16.h>
#include <cstdint>
#include <cstddef>

// ---------------------------------------------------------------------------
// CrossAttention on sm_100 via mma.sync fp16 (HMMA), split fp32 accum.
// R13: out GEMM 2-term (error-budgeted); prep_hv folded into fused_prep.
//   S = X(WqWk^T)Y^T + wv ;  out = (P@Y)@(WvWo) + (bv·Wo+bo)
// ---------------------------------------------------------------------------

#define STAGES 3
#define BK 32
#define TROW 80                     // padded smem row bytes (40 fp16)
#define A_TILE_B (128 * TROW)       // 10240
#define B_TILE_B (256 * TROW)       // 20480

// ---------------- scratch (device globals) ---------------------------------
__device__ __half g_Xh[(size_t)16384*512],  g_Xl[(size_t)16384*512];
__device__ __half g_Yh[(size_t)32768*256],  g_Yl[(size_t)32768*256];
__device__ __half g_YTh[(size_t)16*256*2048], g_YTl[(size_t)16*256*2048];
__device__ __half g_Mh[256*512],  g_Ml[256*512];    // (WqWk^T)^T : [256f, 512e]
__device__ __half g_Nh[512*256],  g_Nl[512*256];    // (WvWo)^T   : [512e, 256f]
__device__ __half g_Th[(size_t)16384*256],  g_Tl[(size_t)16384*256];
__device__ float  g_S[(size_t)16*1024*2048];
__device__ __half g_Ph[(size_t)16384*2048], g_Pl[(size_t)16384*2048];
__device__ __half g_Ch[(size_t)16384*256],  g_Cl[(size_t)16384*256];
__device__ float  g_wv[32768];     // Y @ (Wk @ bq)  (per-key logit bias)
__device__ float  g_ob[512];       // bv @ Wo + bo

// ---------------- helpers ---------------------------------------------------
__device__ __forceinline__ uint32_t smem_u32(const void* p) {
    uint32_t a;
    asm("{ .reg .u64 t; cvta.to.shared.u64 t, %1; cvt.u32.u64 %0, t; }"
        : "=r"(a) : "l"(p));
    return a;
}
__device__ __forceinline__ void cp16(uint32_t dst, const void* src) {
    asm volatile("cp.async.cg.shared.global [%0], [%1], 16;"
                 :: "r"(dst), "l"(src) : "memory");
}
__device__ __forceinline__ void cp_commit() {
    asm volatile("cp.async.commit_group;" ::: "memory");
}
__device__ __forceinline__ void cp_wait1() {
    asm volatile("cp.async.wait_group 1;" ::: "memory");
}
__device__ __forceinline__ void ldm4(uint32_t* r, uint32_t addr) {
    asm volatile("ldmatrix.sync.aligned.m8n8.x4.shared.b16 {%0,%1,%2,%3}, [%4];"
                 : "=r"(r[0]), "=r"(r[1]), "=r"(r[2]), "=r"(r[3]) : "r"(addr));
}
__device__ __forceinline__ void mma16816(float* d, const uint32_t* a,
                                         uint32_t b0, uint32_t b1) {
    asm volatile(
        "mma.sync.aligned.m16n8k16.row.col.f32.f16.f16.f32 "
        "{%0,%1,%2,%3}, {%4,%5,%6,%7}, {%8,%9}, {%0,%1,%2,%3};"
        : "+f"(d[0]), "+f"(d[1]), "+f"(d[2]), "+f"(d[3])
        : "r"(a[0]), "r"(a[1]), "r"(a[2]), "r"(a[3]), "r"(b0), "r"(b1));
}
__device__ __forceinline__ uint32_t pk2h(__half a, __half b) {
    return ((uint32_t)__half_as_ushort(b) << 16) | (uint32_t)__half_as_ushort(a);
}
__device__ __forceinline__ void split_h(float x, __half& hi, __half& lo) {
    hi = __float2half(x);
    lo = __float2half(x - __half2float(hi));
}

// ---------------------------------------------------------------------------
// Split-fp16 GEMM. A:[Mtot,K], B:[Ntot,K] row-major hi/lo.
// TERMS=3: D = AhBh + AlBh + AhBl.  TERMS=2: D = AhBh + AlBh (B hi only).
// Tile 128x256, BK=32, 3-stage cp.async, 16 warps (4Mx4N).
// EPI: 0 = fp32 out, 1 = split-fp16 out. BIAS: 0 none, 1 per-n (z-strided).
// ---------------------------------------------------------------------------
struct GemmArgs {
    const __half *Ah, *Al, *Bh, *Bl;
    const float* bias;
    float* outF;
    __half *outH, *outL;
    int K;
    long long aZ, bZ, outZ;
    int ldc;
    int biasZ;
};

template <int TERMS, int EPI, int BIAS>
__global__ __launch_bounds__(512, 1)
void gemm_mma(GemmArgs g)
{
    constexpr int OFF_AH = 0;
    constexpr int OFF_AL = A_TILE_B;
    constexpr int OFF_BH = 2 * A_TILE_B;
    constexpr int OFF_BL = 2 * A_TILE_B + B_TILE_B;        // TERMS==3 only
    constexpr int STAGE_B = 2 * A_TILE_B + (TERMS == 3 ? 2 : 1) * B_TILE_B;

    extern __shared__ char smem[];
    const uint32_t sm0 = smem_u32(smem);
    const int tid = threadIdx.x, lane = tid & 31, wid = tid >> 5;
    const int wm = wid & 3, wn = wid >> 2;
    const int z = blockIdx.z;
    const int m0 = blockIdx.y * 128, n0 = blockIdx.x * 256;
    const int K = g.K, nkt = K / BK;

    const __half* sAh = g.Ah + (size_t)z * g.aZ + (size_t)m0 * K;
    const __half* sAl = g.Al + (size_t)z * g.aZ + (size_t)m0 * K;
    const __half* sBh = g.Bh + (size_t)z * g.bZ + (size_t)n0 * K;
    const __half* sBl = (TERMS == 3) ? g.Bl + (size_t)z * g.bZ + (size_t)n0 * K : nullptr;
    const float* bp = (BIAS == 1) ? (g.bias + (size_t)z * g.biasZ) : nullptr;

    const int lr = tid >> 2, lc = tid & 3;

    float acc[2][8][4];
#pragma unroll
    for (int i = 0; i < 2; i++)
#pragma unroll
        for (int j = 0; j < 8; j++)
#pragma unroll
            for (int e = 0; e < 4; e++) acc[i][j][e] = 0.0f;

    const uint32_t aoff = (uint32_t)(wm * 32 + (lane & 7) + ((lane >> 3) & 1) * 8) * TROW
                        + (lane >> 4) * 16;
    const uint32_t boff = (uint32_t)(wn * 64 + (lane & 7) + ((lane >> 4) & 1) * 8) * TROW
                        + ((lane >> 3) & 1) * 16;

    auto load_stage = [&](int kt, int s) {
        const uint32_t stb = sm0 + s * STAGE_B;
        const size_t kofs = (size_t)kt * BK;
        const uint32_t drow = (uint32_t)lr * TROW + lc * 16;
        const size_t srow = (size_t)lr * K + kofs + lc * 8;
        cp16(stb + OFF_AH + drow, sAh + srow);
        cp16(stb + OFF_AL + drow, sAl + srow);
#pragma unroll
        for (int h = 0; h < 2; h++) {
            const uint32_t r = lr + h * 128;
            const uint32_t d2 = (uint32_t)r * TROW + lc * 16;
            const size_t s2 = (size_t)r * K + kofs + lc * 8;
            cp16(stb + OFF_BH + d2, sBh + s2);
            if (TERMS == 3) cp16(stb + OFF_BL + d2, sBl + s2);
        }
    };

    auto compute_stage = [&](int s) {
        const uint32_t stb = sm0 + s * STAGE_B;
#pragma unroll
        for (int ks = 0; ks < 2; ks++) {
            uint32_t aH[2][4], aL[2][4], bB[4][4];
#pragma unroll
            for (int mt = 0; mt < 2; mt++) {
                const uint32_t o = aoff + (uint32_t)mt * 16 * TROW + ks * 32;
                ldm4(aH[mt], stb + OFF_AH + o);
                ldm4(aL[mt], stb + OFF_AL + o);
            }
#pragma unroll
            for (int np = 0; np < 4; np++)
                ldm4(bB[np], stb + OFF_BH + boff + (uint32_t)np * 16 * TROW + ks * 32);
            // Ah @ Bh
#pragma unroll
            for (int mt = 0; mt < 2; mt++)
#pragma unroll
                for (int nt = 0; nt < 8; nt++) {
                    const uint32_t* b = &bB[nt >> 1][(nt & 1) * 2];
                    mma16816(acc[mt][nt], aH[mt], b[0], b[1]);
                }
            // Al @ Bh
#pragma unroll
            for (int mt = 0; mt < 2; mt++)
#pragma unroll
                for (int nt = 0; nt < 8; nt++) {
                    const uint32_t* b = &bB[nt >> 1][(nt & 1) * 2];
                    mma16816(acc[mt][nt], aL[mt], b[0], b[1]);
                }
            if (TERMS == 3) {
#pragma unroll
                for (int np = 0; np < 4; np++)
                    ldm4(bB[np], stb + OFF_BL + boff + (uint32_t)np * 16 * TROW + ks * 32);
#pragma unroll
                for (int mt = 0; mt < 2; mt++)
#pragma unroll
                    for (int nt = 0; nt < 8; nt++) {
                        const uint32_t* b = &bB[nt >> 1][(nt & 1) * 2];
                        mma16816(acc[mt][nt], aH[mt], b[0], b[1]);
                    }
            }
        }
    };

#pragma unroll
    for (int s = 0; s < STAGES - 1; s++) { load_stage(s, s); cp_commit(); }
    for (int kt = 0; kt < nkt; kt++) {
        cp_wait1();
        __syncthreads();
        const int nx = kt + STAGES - 1;
        if (nx < nkt) load_stage(nx, nx % STAGES);
        cp_commit();
        compute_stage(kt % STAGES);
    }

    // ---------------- epilogue --------------------------------------------
    const int rr = lane >> 2, rc = (lane & 3) * 2;
#pragma unroll
    for (int mt = 0; mt < 2; mt++) {
#pragma unroll
        for (int nt = 0; nt < 8; nt++) {
            float* d = acc[mt][nt];
            const int m = m0 + wm * 32 + mt * 16 + rr;
            const int n = n0 + wn * 64 + nt * 8 + rc;
            float v[4] = {d[0], d[1], d[2], d[3]};
            if (BIAS == 1) {
                const float b0v = bp[n], b1v = bp[n + 1];
                v[0] += b0v; v[1] += b1v; v[2] += b0v; v[3] += b1v;
            }
            if (EPI == 0) {
                float* o = g.outF + (size_t)z * g.outZ;
                *(float2*)&o[(size_t)m * g.ldc + n]       = make_float2(v[0], v[1]);
                *(float2*)&o[(size_t)(m + 8) * g.ldc + n] = make_float2(v[2], v[3]);
            } else {
                __half hi[4], lo[4];
#pragma unroll
                for (int e = 0; e < 4; e++) split_h(v[e], hi[e], lo[e]);
                __half* oh = g.outH + (size_t)z * g.outZ;
                __half* ol = g.outL + (size_t)z * g.outZ;
                *(uint32_t*)&oh[(size_t)m * g.ldc + n]       = pk2h(hi[0], hi[1]);
                *(uint32_t*)&oh[(size_t)(m + 8) * g.ldc + n] = pk2h(hi[2], hi[3]);
                *(uint32_t*)&ol[(size_t)m * g.ldc + n]       = pk2h(lo[0], lo[1]);
                *(uint32_t*)&ol[(size_t)(m + 8) * g.ldc + n] = pk2h(lo[2], lo[3]);
            }
        }
    }
}

// ---------------------------------------------------------------------------
// Fused prep mega-kernel: blockIdx.x ranges dispatch independent jobs.
//  [0,4096)        splitX
//  [4096,8192)     splitY
//  [8192,10240)    transpose_split (2048 blocks)
//  [10240,10304)   prep_MT (64)
//  [10304,14400)   prep_wv (4096; computes hv = Wk@bq locally)
//  [14400,14464)   prep_NT (64)
//  [14464]         prep_ob (1)
// ---------------------------------------------------------------------------
#define FP_SPLITX0   0
#define FP_SPLITY0   4096
#define FP_TRANS0    8192
#define FP_MT0       10240
#define FP_WV0       10304
#define FP_NT0       14400
#define FP_OB0       14464
#define FP_NBLK      14465

struct PrepArgs {
    const float *X, *Y, *Wq, *Wk, *Wv, *Wo, *bq, *bv, *bo;
    __half *Xh, *Xl, *Yh, *Yl, *YTh, *YTl, *Mh, *Ml, *Nh, *Nl;
    float *wv, *ob;
};

__global__ __launch_bounds__(256)
void fused_prep(PrepArgs p)
{
    __shared__ __align__(16) char smbuf[24960];
    const int blk = blockIdx.x;
    const int tid = threadIdx.x;

    if (blk < FP_SPLITY0) {
        // ---- splitX
        const size_t id = (size_t)(blk - FP_SPLITX0) * 256 + tid;
        float v[8];
        *(float4*)&v[0] = ((const float4*)p.X)[id * 2];
        *(float4*)&v[4] = ((const float4*)p.X)[id * 2 + 1];
        __half hi[8], lo[8];
#pragma unroll
        for (int e = 0; e < 8; e++) split_h(v[e], hi[e], lo[e]);
        uint4 hv4, lv4;
        hv4.x = pk2h(hi[0],hi[1]); hv4.y = pk2h(hi[2],hi[3]);
        hv4.z = pk2h(hi[4],hi[5]); hv4.w = pk2h(hi[6],hi[7]);
        lv4.x = pk2h(lo[0],lo[1]); lv4.y = pk2h(lo[2],lo[3]);
        lv4.z = pk2h(lo[4],lo[5]); lv4.w = pk2h(lo[6],lo[7]);
        *(uint4*)&p.Xh[id * 8] = hv4;
        *(uint4*)&p.Xl[id * 8] = lv4;
    } else if (blk < FP_TRANS0) {
        // ---- splitY
        const size_t id = (size_t)(blk - FP_SPLITY0) * 256 + tid;
        float v[8];
        *(float4*)&v[0] = ((const float4*)p.Y)[id * 2];
        *(float4*)&v[4] = ((const float4*)p.Y)[id * 2 + 1];
        __half hi[8], lo[8];
#pragma unroll
        for (int e = 0; e < 8; e++) split_h(v[e], hi[e], lo[e]);
        uint4 hv4, lv4;
        hv4.x = pk2h(hi[0],hi[1]); hv4.y = pk2h(hi[2],hi[3]);
        hv4.z = pk2h(hi[4],hi[5]); hv4.w = pk2h(hi[6],hi[7]);
        lv4.x = pk2h(lo[0],lo[1]); lv4.y = pk2h(lo[2],lo[3]);
        lv4.z = pk2h(lo[4],lo[5]); lv4.w = pk2h(lo[6],lo[7]);
        *(uint4*)&p.Yh[id * 8] = hv4;
        *(uint4*)&p.Yl[id * 8] = lv4;
    } else if (blk < FP_MT0) {
        // ---- transpose_split: Y [2048,256] -> Y^T split [256,2048] x16
        float (*t)[65] = (float(*)[65])smbuf;            // 64x65 floats
        const int idx = blk - FP_TRANS0;
        const int z  = idx >> 7;
        const int r7 = idx & 127;
        const int k0 = (r7 >> 2) * 64;
        const int f0 = (r7 & 3) * 64;
        const float* Yb = p.Y + (size_t)z * 2048 * 256;

        for (int i = tid; i < 64 * 16; i += 256) {
            const int r = i >> 4, c4 = i & 15;
            const float4 v = *(const float4*)&Yb[(size_t)(k0 + r) * 256 + f0 + c4 * 4];
            t[r][c4 * 4 + 0] = v.x; t[r][c4 * 4 + 1] = v.y;
            t[r][c4 * 4 + 2] = v.z; t[r][c4 * 4 + 3] = v.w;
        }
        __syncthreads();
        __half* thb = p.YTh + (size_t)z * 256 * 2048;
        __half* tlb = p.YTl + (size_t)z * 256 * 2048;
        for (int i = tid; i < 64 * 16; i += 256) {
            const int f = i >> 4, c4 = i & 15;
            __half hi[4], lo[4];
#pragma unroll
            for (int e = 0; e < 4; e++) split_h(t[c4 * 4 + e][f], hi[e], lo[e]);
            uint2 hv2, lv2;
            hv2.x = pk2h(hi[0], hi[1]); hv2.y = pk2h(hi[2], hi[3]);
            lv2.x = pk2h(lo[0], lo[1]); lv2.y = pk2h(lo[2], lo[3]);
            *(uint2*)&thb[(size_t)(f0 + f) * 2048 + k0 + c4 * 4] = hv2;
            *(uint2*)&tlb[(size_t)(f0 + f) * 2048 + k0 + c4 * 4] = lv2;
        }
    } else if (blk < FP_WV0) {
        // ---- prep_MT: MT[f,e] = Wk[f,:]·Wq[e,:]  (32f x 64e tile)
        float (*As)[65] = (float(*)[65])smbuf;                    // 32x65
        float (*Bs)[65] = (float(*)[65])(smbuf + 32*65*4);        // 64x65
        const int idx = blk - FP_MT0;
        const int e0 = (idx & 7) * 64, f0 = (idx >> 3) * 32;
        const int tx = tid & 15, ty = tid >> 4;

        float acc[2][4] = {};
        for (int a0 = 0; a0 < 512; a0 += 64) {
#pragma unroll
            for (int it = 0; it < 2; it++) {
                const int j = tid + it * 256;
                const int r = j >> 4, c4 = j & 15;
                const float4 v = *(const float4*)&p.Wk[(size_t)(f0 + r) * 512 + a0 + c4 * 4];
                As[r][c4*4+0] = v.x; As[r][c4*4+1] = v.y;
                As[r][c4*4+2] = v.z; As[r][c4*4+3] = v.w;
            }
#pragma unroll
            for (int it = 0; it < 4; it++) {
                const int j = tid + it * 256;
                const int r = j >> 4, c4 = j & 15;
                const float4 v = *(const float4*)&p.Wq[(size_t)(e0 + r) * 512 + a0 + c4 * 4];
                Bs[r][c4*4+0] = v.x; Bs[r][c4*4+1] = v.y;
                Bs[r][c4*4+2] = v.z; Bs[r][c4*4+3] = v.w;
            }
            __syncthreads();
#pragma unroll 8
            for (int a = 0; a < 64; a++) {
                const float a0v = As[ty*2][a], a1v = As[ty*2+1][a];
                float b[4];
#pragma unroll
                for (int j = 0; j < 4; j++) b[j] = Bs[tx*4+j][a];
#pragma unroll
                for (int j = 0; j < 4; j++) {
                    acc[0][j] = fmaf(a0v, b[j], acc[0][j]);
                    acc[1][j] = fmaf(a1v, b[j], acc[1][j]);
                }
            }
            __syncthreads();
        }
#pragma unroll
        for (int i = 0; i < 2; i++) {
            const int f = f0 + ty*2 + i;
            __half hi[4], lo[4];
#pragma unroll
            for (int j = 0; j < 4; j++) split_h(acc[i][j], hi[j], lo[j]);
            uint2 hv2, lv2;
            hv2.x = pk2h(hi[0], hi[1]); hv2.y = pk2h(hi[2], hi[3]);
            lv2.x = pk2h(lo[0], lo[1]); lv2.y = pk2h(lo[2], lo[3]);
            *(uint2*)&p.Mh[(size_t)f * 512 + e0 + tx*4] = hv2;
            *(uint2*)&p.Ml[(size_t)f * 512 + e0 + tx*4] = lv2;
        }
    } else if (blk < FP_NT0) {
        // ---- prep_wv: compute hv = Wk@bq locally, then wv[r] = Y[r,:]·hv
        float* hs = (float*)smbuf;     // 256 floats
        {
            // each thread computes hv[tid] = Wk[tid,:] . bq
            const float* wkrow = p.Wk + (size_t)tid * 512;
            float s = 0.0f;
#pragma unroll 4
            for (int a = 0; a < 512; a += 4) {
                const float4 w4 = *(const float4*)&wkrow[a];
                const float4 b4 = *(const float4*)&p.bq[a];
                s = fmaf(w4.x, b4.x, s); s = fmaf(w4.y, b4.y, s);
                s = fmaf(w4.z, b4.z, s); s = fmaf(w4.w, b4.w, s);
            }
            hs[tid] = s;
        }
        __syncthreads();
        const int lane = tid & 31;
        const int w = tid >> 5;
        const size_t r = (size_t)(blk - FP_WV0) * 8 + w;
        const float* row = p.Y + r * 256;
        float s = 0.0f;
#pragma unroll
        for (int j = 0; j < 8; j++) s = fmaf(row[lane * 8 + j], hs[lane * 8 + j], s);
#pragma unroll
        for (int o = 16; o; o >>= 1) s += __shfl_xor_sync(0xffffffffu, s, o);
        if (lane == 0) p.wv[r] = s;
    } else if (blk < FP_OB0) {
        // ---- prep_NT: NT[e,f] = Wv[f,:]·Wo[:,e]  (64e x 32f tile)
        float (*Os)[65] = (float(*)[65])smbuf;                    // 64x65
        float (*Vs)[65] = (float(*)[65])(smbuf + 64*65*4);        // 32x65
        const int idx = blk - FP_NT0;
        const int f0 = (idx & 7) * 32, e0 = (idx >> 3) * 64;
        const int tx = tid & 15, ty = tid >> 4;

        float acc[4][2] = {};
        for (int a0 = 0; a0 < 512; a0 += 64) {
#pragma unroll
            for (int it = 0; it < 4; it++) {
                const int j = tid + it * 256;
                const int r = j >> 4, c4 = j & 15;
                const float4 v = *(const float4*)&p.Wo[(size_t)(a0 + r) * 512 + e0 + c4 * 4];
                Os[r][c4*4+0] = v.x; Os[r][c4*4+1] = v.y;
                Os[r][c4*4+2] = v.z; Os[r][c4*4+3] = v.w;
            }
#pragma unroll
            for (int it = 0; it < 2; it++) {
                const int j = tid + it * 256;
                const int r = j >> 4, c4 = j & 15;
                const float4 v = *(const float4*)&p.Wv[(size_t)(f0 + r) * 512 + a0 + c4 * 4];
                Vs[r][c4*4+0] = v.x; Vs[r][c4*4+1] = v.y;
                Vs[r][c4*4+2] = v.z; Vs[r][c4*4+3] = v.w;
            }
            __syncthreads();
#pragma unroll 8
            for (int a = 0; a < 64; a++) {
                float e4[4], fv0, fv1;
#pragma unroll
                for (int i = 0; i < 4; i++) e4[i] = Os[a][ty*4+i];
                fv0 = Vs[tx*2][a]; fv1 = Vs[tx*2+1][a];
#pragma unroll
                for (int i = 0; i < 4; i++) {
                    acc[i][0] = fmaf(e4[i], fv0, acc[i][0]);
                    acc[i][1] = fmaf(e4[i], fv1, acc[i][1]);
                }
            }
            __syncthreads();
        }
#pragma unroll
        for (int i = 0; i < 4; i++) {
            const int e = e0 + ty*4 + i;
            __half hi[2], lo[2];
#pragma unroll
            for (int j = 0; j < 2; j++) split_h(acc[i][j], hi[j], lo[j]);
            *(uint32_t*)&p.Nh[(size_t)e * 256 + f0 + tx*2] = pk2h(hi[0], hi[1]);
            *(uint32_t*)&p.Nl[(size_t)e * 256 + f0 + tx*2] = pk2h(lo[0], lo[1]);
        }
    } else {
        // ---- prep_ob: ob[e] = bo[e] + bv·Wo[:,e]
#pragma unroll
        for (int half = 0; half < 2; half++) {
            const int e = tid + half * 256;
            float s = p.bo[e];
            for (int a = 0; a < 512; a++)
                s = fmaf(p.bv[a], p.Wo[(size_t)a * 512 + e], s);
            p.ob[e] = s;
        }
    }
}

// ---------------------------------------------------------------------------
// Softmax over 2048-col fp32 rows -> hi/lo fp16 row-major
// ---------------------------------------------------------------------------
__global__ __launch_bounds__(256)
void softmax_split(const float* __restrict__ S, __half* __restrict__ Sh,
                   __half* __restrict__ Sl)
{
    const size_t r = blockIdx.x;
    const float* row = S + r * 2048;
    const int tid = threadIdx.x;
    const int c0 = tid * 8;

    float v[8];
    *(float4*)&v[0] = *(const float4*)&row[c0];
    *(float4*)&v[4] = *(const float4*)&row[c0 + 4];

    __shared__ float red[8];
    float m = v[0];
#pragma unroll
    for (int e = 1; e < 8; e++) m = fmaxf(m, v[e]);
#pragma unroll
    for (int o = 16; o; o >>= 1) m = fmaxf(m, __shfl_xor_sync(0xffffffffu, m, o));
    if ((tid & 31) == 0) red[tid >> 5] = m;
    __syncthreads();
    float mx = red[0];
#pragma unroll
    for (int i = 1; i < 8; i++) mx = fmaxf(mx, red[i]);
    __syncthreads();

    float s = 0.0f;
#pragma unroll
    for (int e = 0; e < 8; e++) { v[e] = __expf(v[e] - mx); s += v[e]; }
#pragma unroll
    for (int o = 16; o; o >>= 1) s += __shfl_xor_sync(0xffffffffu, s, o);
    if ((tid & 31) == 0) red[tid >> 5] = s;
    __syncthreads();
    float st = 0.0f;
#pragma unroll
    for (int i = 0; i < 8; i++) st += red[i];
    const float inv = 1.0f / st;

    __half hi[8], lo[8];
#pragma unroll
    for (int e = 0; e < 8; e++) split_h(v[e] * inv, hi[e], lo[e]);
    uint4 hv4, lv4;
    hv4.x = pk2h(hi[0],hi[1]); hv4.y = pk2h(hi[2],hi[3]);
    hv4.z = pk2h(hi[4],hi[5]); hv4.w = pk2h(hi[6],hi[7]);
    lv4.x = pk2h(lo[0],lo[1]); lv4.y = pk2h(lo[2],lo[3]);
    lv4.z = pk2h(lo[4],lo[5]); lv4.w = pk2h(lo[6],lo[7]);
    *(uint4*)&Sh[r * 2048 + c0] = hv4;
    *(uint4*)&Sl[r * 2048 + c0] = lv4;
}

// ---------------------------------------------------------------------------
// Launch
// ---------------------------------------------------------------------------
extern "C" void kernel_launch(void* const* d_in, const int* in_sizes, int n_in,
                              void* d_out, int out_size)
{
    const float* X  = (const float*)d_in[0];
    const float* Y  = (const float*)d_in[1];
    const float* Wq = (const float*)d_in[2];
    const float* bq = (const float*)d_in[3];
    const float* Wk = (const float*)d_in[4];
    const float* Wv = (const float*)d_in[6];
    const float* bv = (const float*)d_in[7];
    const float* Wo = (const float*)d_in[8];
    const float* bo = (const float*)d_in[9];
    float* out = (float*)d_out;

    constexpr int SMEM3 = STAGES * (2 * A_TILE_B + 2 * B_TILE_B);   // 184320
    constexpr int SMEM2 = STAGES * (2 * A_TILE_B + 1 * B_TILE_B);   // 122880
    cudaFuncSetAttribute(gemm_mma<3,0,1>, cudaFuncAttributeMaxDynamicSharedMemorySize, SMEM3);
    cudaFuncSetAttribute(gemm_mma<3,1,0>, cudaFuncAttributeMaxDynamicSharedMemorySize, SMEM3);
    cudaFuncSetAttribute(gemm_mma<2,1,0>, cudaFuncAttributeMaxDynamicSharedMemorySize, SMEM2);
    cudaFuncSetAttribute(gemm_mma<2,0,1>, cudaFuncAttributeMaxDynamicSharedMemorySize, SMEM2);

    __half *Xh,*Xl,*Yh,*Yl,*YTh,*YTl,*Mh,*Ml,*Nh,*Nl,*Th,*Tl,*Ph,*Pl,*Ch,*Cl;
    float *S,*wv,*ob;
    cudaGetSymbolAddress((void**)&Xh, g_Xh);   cudaGetSymbolAddress((void**)&Xl, g_Xl);
    cudaGetSymbolAddress((void**)&Yh, g_Yh);   cudaGetSymbolAddress((void**)&Yl, g_Yl);
    cudaGetSymbolAddress((void**)&YTh, g_YTh); cudaGetSymbolAddress((void**)&YTl, g_YTl);
    cudaGetSymbolAddress((void**)&Mh, g_Mh);   cudaGetSymbolAddress((void**)&Ml, g_Ml);
    cudaGetSymbolAddress((void**)&Nh, g_Nh);   cudaGetSymbolAddress((void**)&Nl, g_Nl);
    cudaGetSymbolAddress((void**)&Th, g_Th);   cudaGetSymbolAddress((void**)&Tl, g_Tl);
    cudaGetSymbolAddress((void**)&Ph, g_Ph);   cudaGetSymbolAddress((void**)&Pl, g_Pl);
    cudaGetSymbolAddress((void**)&Ch, g_Ch);   cudaGetSymbolAddress((void**)&Cl, g_Cl);
    cudaGetSymbolAddress((void**)&S, g_S);
    cudaGetSymbolAddress((void**)&wv, g_wv);
    cudaGetSymbolAddress((void**)&ob, g_ob);

    // 1: fused prep (everything independent, one launch; wv computes hv inline)
    {
        PrepArgs p{X, Y, Wq, Wk, Wv, Wo, bq, bv, bo,
                   Xh, Xl, Yh, Yl, YTh, YTl, Mh, Ml, Nh, Nl,
                   wv, ob};
        fused_prep<<<FP_NBLK, 256>>>(p);
    }
    // 2: T = X @ M -> split [16384,256]   (3-term)
    {
        GemmArgs a{Xh, Xl, Mh, Ml, nullptr, nullptr, Th, Tl,
                   512, 0, 0, 0, 256, 0};
        gemm_mma<3,1,0><<<dim3(1,128,1), 512, SMEM3>>>(a);
    }
    // 3: S = T_z @ Y_z^T + wv -> fp32 [1024,2048] x16   (3-term)
    {
        GemmArgs a{Th, Tl, Yh, Yl, wv, S, nullptr, nullptr,
                   256, (long long)1024*256, (long long)2048*256,
                   (long long)1024*2048, 2048, 2048};
        gemm_mma<3,0,1><<<dim3(8,8,16), 512, SMEM3>>>(a);
    }
    // 4: softmax -> P split
    softmax_split<<<16384, 256>>>(S, Ph, Pl);
    // 5: C = (Ph+Pl) @ Yh -> split [1024,256] x16   (2-term)
    {
        GemmArgs a{Ph, Pl, YTh, nullptr, nullptr, nullptr, Ch, Cl,
                   2048, (long long)1024*2048, (long long)256*2048,
                   (long long)1024*256, 256, 0};
        gemm_mma<2,1,0><<<dim3(1,8,16), 512, SMEM2>>>(a);
    }
    // 6: out = (Ch+Cl) @ Nh + ob -> fp32 [16384,512]   (2-term)
    {
        GemmArgs a{Ch, Cl, Nh, nullptr, ob, out, nullptr, nullptr,
                   256, 0, 0, 0, 512, 0};
        gemm_mma<2,0,1><<<dim3(2,128,1), 512, SMEM2>>>(a);
    }
}

// round 14
// speedup vs baseline: 1.8047x; 1.8047x over previous
#include <cuda_runtime.h>
#include <cuda_fp16.h>
#include <cstdint>
#include <cstddef>

// ---------------------------------------------------------------------------
// CrossAttention on sm_100 via mma.sync fp16 (HMMA), split fp32 accum.
// R14: R12 structure (separate prep_hv; fused_prep reads precomputed hv)
// + R13's validated 2-term out GEMM. (R13's inlined hv cost 2.1GB of L2
// traffic — reverted.)
//   S = X(WqWk^T)Y^T + wv ;  out = (P@Y)@(WvWo) + (bv·Wo+bo)
// ---------------------------------------------------------------------------

#define STAGES 3
#define BK 32
#define TROW 80                     // padded smem row bytes (40 fp16)
#define A_TILE_B (128 * TROW)       // 10240
#define B_TILE_B (256 * TROW)       // 20480

// ---------------- scratch (device globals) ---------------------------------
__device__ __half g_Xh[(size_t)16384*512],  g_Xl[(size_t)16384*512];
__device__ __half g_Yh[(size_t)32768*256],  g_Yl[(size_t)32768*256];
__device__ __half g_YTh[(size_t)16*256*2048], g_YTl[(size_t)16*256*2048];
__device__ __half g_Mh[256*512],  g_Ml[256*512];    // (WqWk^T)^T : [256f, 512e]
__device__ __half g_Nh[512*256],  g_Nl[512*256];    // (WvWo)^T   : [512e, 256f]
__device__ __half g_Th[(size_t)16384*256],  g_Tl[(size_t)16384*256];
__device__ float  g_S[(size_t)16*1024*2048];
__device__ __half g_Ph[(size_t)16384*2048], g_Pl[(size_t)16384*2048];
__device__ __half g_Ch[(size_t)16384*256],  g_Cl[(size_t)16384*256];
__device__ float  g_hv[256];       // Wk @ bq
__device__ float  g_wv[32768];     // Y @ (Wk @ bq)  (per-key logit bias)
__device__ float  g_ob[512];       // bv @ Wo + bo

// ---------------- helpers ---------------------------------------------------
__device__ __forceinline__ uint32_t smem_u32(const void* p) {
    uint32_t a;
    asm("{ .reg .u64 t; cvta.to.shared.u64 t, %1; cvt.u32.u64 %0, t; }"
        : "=r"(a) : "l"(p));
    return a;
}
__device__ __forceinline__ void cp16(uint32_t dst, const void* src) {
    asm volatile("cp.async.cg.shared.global [%0], [%1], 16;"
                 :: "r"(dst), "l"(src) : "memory");
}
__device__ __forceinline__ void cp_commit() {
    asm volatile("cp.async.commit_group;" ::: "memory");
}
__device__ __forceinline__ void cp_wait1() {
    asm volatile("cp.async.wait_group 1;" ::: "memory");
}
__device__ __forceinline__ void ldm4(uint32_t* r, uint32_t addr) {
    asm volatile("ldmatrix.sync.aligned.m8n8.x4.shared.b16 {%0,%1,%2,%3}, [%4];"
                 : "=r"(r[0]), "=r"(r[1]), "=r"(r[2]), "=r"(r[3]) : "r"(addr));
}
__device__ __forceinline__ void mma16816(float* d, const uint32_t* a,
                                         uint32_t b0, uint32_t b1) {
    asm volatile(
        "mma.sync.aligned.m16n8k16.row.col.f32.f16.f16.f32 "
        "{%0,%1,%2,%3}, {%4,%5,%6,%7}, {%8,%9}, {%0,%1,%2,%3};"
        : "+f"(d[0]), "+f"(d[1]), "+f"(d[2]), "+f"(d[3])
        : "r"(a[0]), "r"(a[1]), "r"(a[2]), "r"(a[3]), "r"(b0), "r"(b1));
}
__device__ __forceinline__ uint32_t pk2h(__half a, __half b) {
    return ((uint32_t)__half_as_ushort(b) << 16) | (uint32_t)__half_as_ushort(a);
}
__device__ __forceinline__ void split_h(float x, __half& hi, __half& lo) {
    hi = __float2half(x);
    lo = __float2half(x - __half2float(hi));
}

// ---------------------------------------------------------------------------
// Split-fp16 GEMM. A:[Mtot,K], B:[Ntot,K] row-major hi/lo.
// TERMS=3: D = AhBh + AlBh + AhBl.  TERMS=2: D = AhBh + AlBh (B hi only).
// Tile 128x256, BK=32, 3-stage cp.async, 16 warps (4Mx4N).
// EPI: 0 = fp32 out, 1 = split-fp16 out. BIAS: 0 none, 1 per-n (z-strided).
// ---------------------------------------------------------------------------
struct GemmArgs {
    const __half *Ah, *Al, *Bh, *Bl;
    const float* bias;
    float* outF;
    __half *outH, *outL;
    int K;
    long long aZ, bZ, outZ;
    int ldc;
    int biasZ;
};

template <int TERMS, int EPI, int BIAS>
__global__ __launch_bounds__(512, 1)
void gemm_mma(GemmArgs g)
{
    constexpr int OFF_AH = 0;
    constexpr int OFF_AL = A_TILE_B;
    constexpr int OFF_BH = 2 * A_TILE_B;
    constexpr int OFF_BL = 2 * A_TILE_B + B_TILE_B;        // TERMS==3 only
    constexpr int STAGE_B = 2 * A_TILE_B + (TERMS == 3 ? 2 : 1) * B_TILE_B;

    extern __shared__ char smem[];
    const uint32_t sm0 = smem_u32(smem);
    const int tid = threadIdx.x, lane = tid & 31, wid = tid >> 5;
    const int wm = wid & 3, wn = wid >> 2;
    const int z = blockIdx.z;
    const int m0 = blockIdx.y * 128, n0 = blockIdx.x * 256;
    const int K = g.K, nkt = K / BK;

    const __half* sAh = g.Ah + (size_t)z * g.aZ + (size_t)m0 * K;
    const __half* sAl = g.Al + (size_t)z * g.aZ + (size_t)m0 * K;
    const __half* sBh = g.Bh + (size_t)z * g.bZ + (size_t)n0 * K;
    const __half* sBl = (TERMS == 3) ? g.Bl + (size_t)z * g.bZ + (size_t)n0 * K : nullptr;
    const float* bp = (BIAS == 1) ? (g.bias + (size_t)z * g.biasZ) : nullptr;

    const int lr = tid >> 2, lc = tid & 3;

    float acc[2][8][4];
#pragma unroll
    for (int i = 0; i < 2; i++)
#pragma unroll
        for (int j = 0; j < 8; j++)
#pragma unroll
            for (int e = 0; e < 4; e++) acc[i][j][e] = 0.0f;

    const uint32_t aoff = (uint32_t)(wm * 32 + (lane & 7) + ((lane >> 3) & 1) * 8) * TROW
                        + (lane >> 4) * 16;
    const uint32_t boff = (uint32_t)(wn * 64 + (lane & 7) + ((lane >> 4) & 1) * 8) * TROW
                        + ((lane >> 3) & 1) * 16;

    auto load_stage = [&](int kt, int s) {
        const uint32_t stb = sm0 + s * STAGE_B;
        const size_t kofs = (size_t)kt * BK;
        const uint32_t drow = (uint32_t)lr * TROW + lc * 16;
        const size_t srow = (size_t)lr * K + kofs + lc * 8;
        cp16(stb + OFF_AH + drow, sAh + srow);
        cp16(stb + OFF_AL + drow, sAl + srow);
#pragma unroll
        for (int h = 0; h < 2; h++) {
            const uint32_t r = lr + h * 128;
            const uint32_t d2 = (uint32_t)r * TROW + lc * 16;
            const size_t s2 = (size_t)r * K + kofs + lc * 8;
            cp16(stb + OFF_BH + d2, sBh + s2);
            if (TERMS == 3) cp16(stb + OFF_BL + d2, sBl + s2);
        }
    };

    auto compute_stage = [&](int s) {
        const uint32_t stb = sm0 + s * STAGE_B;
#pragma unroll
        for (int ks = 0; ks < 2; ks++) {
            uint32_t aH[2][4], aL[2][4], bB[4][4];
#pragma unroll
            for (int mt = 0; mt < 2; mt++) {
                const uint32_t o = aoff + (uint32_t)mt * 16 * TROW + ks * 32;
                ldm4(aH[mt], stb + OFF_AH + o);
                ldm4(aL[mt], stb + OFF_AL + o);
            }
#pragma unroll
            for (int np = 0; np < 4; np++)
                ldm4(bB[np], stb + OFF_BH + boff + (uint32_t)np * 16 * TROW + ks * 32);
            // Ah @ Bh
#pragma unroll
            for (int mt = 0; mt < 2; mt++)
#pragma unroll
                for (int nt = 0; nt < 8; nt++) {
                    const uint32_t* b = &bB[nt >> 1][(nt & 1) * 2];
                    mma16816(acc[mt][nt], aH[mt], b[0], b[1]);
                }
            // Al @ Bh
#pragma unroll
            for (int mt = 0; mt < 2; mt++)
#pragma unroll
                for (int nt = 0; nt < 8; nt++) {
                    const uint32_t* b = &bB[nt >> 1][(nt & 1) * 2];
                    mma16816(acc[mt][nt], aL[mt], b[0], b[1]);
                }
            if (TERMS == 3) {
#pragma unroll
                for (int np = 0; np < 4; np++)
                    ldm4(bB[np], stb + OFF_BL + boff + (uint32_t)np * 16 * TROW + ks * 32);
#pragma unroll
                for (int mt = 0; mt < 2; mt++)
#pragma unroll
                    for (int nt = 0; nt < 8; nt++) {
                        const uint32_t* b = &bB[nt >> 1][(nt & 1) * 2];
                        mma16816(acc[mt][nt], aH[mt], b[0], b[1]);
                    }
            }
        }
    };

#pragma unroll
    for (int s = 0; s < STAGES - 1; s++) { load_stage(s, s); cp_commit(); }
    for (int kt = 0; kt < nkt; kt++) {
        cp_wait1();
        __syncthreads();
        const int nx = kt + STAGES - 1;
        if (nx < nkt) load_stage(nx, nx % STAGES);
        cp_commit();
        compute_stage(kt % STAGES);
    }

    // ---------------- epilogue --------------------------------------------
    const int rr = lane >> 2, rc = (lane & 3) * 2;
#pragma unroll
    for (int mt = 0; mt < 2; mt++) {
#pragma unroll
        for (int nt = 0; nt < 8; nt++) {
            float* d = acc[mt][nt];
            const int m = m0 + wm * 32 + mt * 16 + rr;
            const int n = n0 + wn * 64 + nt * 8 + rc;
            float v[4] = {d[0], d[1], d[2], d[3]};
            if (BIAS == 1) {
                const float b0v = bp[n], b1v = bp[n + 1];
                v[0] += b0v; v[1] += b1v; v[2] += b0v; v[3] += b1v;
            }
            if (EPI == 0) {
                float* o = g.outF + (size_t)z * g.outZ;
                *(float2*)&o[(size_t)m * g.ldc + n]       = make_float2(v[0], v[1]);
                *(float2*)&o[(size_t)(m + 8) * g.ldc + n] = make_float2(v[2], v[3]);
            } else {
                __half hi[4], lo[4];
#pragma unroll
                for (int e = 0; e < 4; e++) split_h(v[e], hi[e], lo[e]);
                __half* oh = g.outH + (size_t)z * g.outZ;
                __half* ol = g.outL + (size_t)z * g.outZ;
                *(uint32_t*)&oh[(size_t)m * g.ldc + n]       = pk2h(hi[0], hi[1]);
                *(uint32_t*)&oh[(size_t)(m + 8) * g.ldc + n] = pk2h(hi[2], hi[3]);
                *(uint32_t*)&ol[(size_t)m * g.ldc + n]       = pk2h(lo[0], lo[1]);
                *(uint32_t*)&ol[(size_t)(m + 8) * g.ldc + n] = pk2h(lo[2], lo[3]);
            }
        }
    }
}

// ---------------------------------------------------------------------------
// prep_hv: hv[f] = Wk[f,:] . bq  (single block; launched before fused prep)
// ---------------------------------------------------------------------------
__global__ __launch_bounds__(256)
void prep_hv(const float* __restrict__ Wk, const float* __restrict__ bq,
             float* __restrict__ hv)
{
    const int f = threadIdx.x;
    float s = 0.0f;
    for (int a = 0; a < 512; a++) s = fmaf(Wk[(size_t)f * 512 + a], bq[a], s);
    hv[f] = s;
}

// ---------------------------------------------------------------------------
// Fused prep mega-kernel: blockIdx.x ranges dispatch independent jobs.
//  [0,4096)        splitX
//  [4096,8192)     splitY
//  [8192,10240)    transpose_split (2048 blocks)
//  [10240,10304)   prep_MT (64)
//  [10304,14400)   prep_wv (4096; reads precomputed hv)
//  [14400,14464)   prep_NT (64)
//  [14464]         prep_ob (1)
// ---------------------------------------------------------------------------
#define FP_SPLITX0   0
#define FP_SPLITY0   4096
#define FP_TRANS0    8192
#define FP_MT0       10240
#define FP_WV0       10304
#define FP_NT0       14400
#define FP_OB0       14464
#define FP_NBLK      14465

struct PrepArgs {
    const float *X, *Y, *Wq, *Wk, *Wv, *Wo, *bv, *bo, *hv;
    __half *Xh, *Xl, *Yh, *Yl, *YTh, *YTl, *Mh, *Ml, *Nh, *Nl;
    float *wv, *ob;
};

__global__ __launch_bounds__(256)
void fused_prep(PrepArgs p)
{
    __shared__ __align__(16) char smbuf[24960];
    const int blk = blockIdx.x;
    const int tid = threadIdx.x;

    if (blk < FP_SPLITY0) {
        // ---- splitX
        const size_t id = (size_t)(blk - FP_SPLITX0) * 256 + tid;
        float v[8];
        *(float4*)&v[0] = ((const float4*)p.X)[id * 2];
        *(float4*)&v[4] = ((const float4*)p.X)[id * 2 + 1];
        __half hi[8], lo[8];
#pragma unroll
        for (int e = 0; e < 8; e++) split_h(v[e], hi[e], lo[e]);
        uint4 hv4, lv4;
        hv4.x = pk2h(hi[0],hi[1]); hv4.y = pk2h(hi[2],hi[3]);
        hv4.z = pk2h(hi[4],hi[5]); hv4.w = pk2h(hi[6],hi[7]);
        lv4.x = pk2h(lo[0],lo[1]); lv4.y = pk2h(lo[2],lo[3]);
        lv4.z = pk2h(lo[4],lo[5]); lv4.w = pk2h(lo[6],lo[7]);
        *(uint4*)&p.Xh[id * 8] = hv4;
        *(uint4*)&p.Xl[id * 8] = lv4;
    } else if (blk < FP_TRANS0) {
        // ---- splitY
        const size_t id = (size_t)(blk - FP_SPLITY0) * 256 + tid;
        float v[8];
        *(float4*)&v[0] = ((const float4*)p.Y)[id * 2];
        *(float4*)&v[4] = ((const float4*)p.Y)[id * 2 + 1];
        __half hi[8], lo[8];
#pragma unroll
        for (int e = 0; e < 8; e++) split_h(v[e], hi[e], lo[e]);
        uint4 hv4, lv4;
        hv4.x = pk2h(hi[0],hi[1]); hv4.y = pk2h(hi[2],hi[3]);
        hv4.z = pk2h(hi[4],hi[5]); hv4.w = pk2h(hi[6],hi[7]);
        lv4.x = pk2h(lo[0],lo[1]); lv4.y = pk2h(lo[2],lo[3]);
        lv4.z = pk2h(lo[4],lo[5]); lv4.w = pk2h(lo[6],lo[7]);
        *(uint4*)&p.Yh[id * 8] = hv4;
        *(uint4*)&p.Yl[id * 8] = lv4;
    } else if (blk < FP_MT0) {
        // ---- transpose_split: Y [2048,256] -> Y^T split [256,2048] x16
        float (*t)[65] = (float(*)[65])smbuf;            // 64x65 floats
        const int idx = blk - FP_TRANS0;
        const int z  = idx >> 7;
        const int r7 = idx & 127;
        const int k0 = (r7 >> 2) * 64;
        const int f0 = (r7 & 3) * 64;
        const float* Yb = p.Y + (size_t)z * 2048 * 256;

        for (int i = tid; i < 64 * 16; i += 256) {
            const int r = i >> 4, c4 = i & 15;
            const float4 v = *(const float4*)&Yb[(size_t)(k0 + r) * 256 + f0 + c4 * 4];
            t[r][c4 * 4 + 0] = v.x; t[r][c4 * 4 + 1] = v.y;
            t[r][c4 * 4 + 2] = v.z; t[r][c4 * 4 + 3] = v.w;
        }
        __syncthreads();
        __half* thb = p.YTh + (size_t)z * 256 * 2048;
        __half* tlb = p.YTl + (size_t)z * 256 * 2048;
        for (int i = tid; i < 64 * 16; i += 256) {
            const int f = i >> 4, c4 = i & 15;
            __half hi[4], lo[4];
#pragma unroll
            for (int e = 0; e < 4; e++) split_h(t[c4 * 4 + e][f], hi[e], lo[e]);
            uint2 hv2, lv2;
            hv2.x = pk2h(hi[0], hi[1]); hv2.y = pk2h(hi[2], hi[3]);
            lv2.x = pk2h(lo[0], lo[1]); lv2.y = pk2h(lo[2], lo[3]);
            *(uint2*)&thb[(size_t)(f0 + f) * 2048 + k0 + c4 * 4] = hv2;
            *(uint2*)&tlb[(size_t)(f0 + f) * 2048 + k0 + c4 * 4] = lv2;
        }
    } else if (blk < FP_WV0) {
        // ---- prep_MT: MT[f,e] = Wk[f,:]·Wq[e,:]  (32f x 64e tile)
        float (*As)[65] = (float(*)[65])smbuf;                    // 32x65
        float (*Bs)[65] = (float(*)[65])(smbuf + 32*65*4);        // 64x65
        const int idx = blk - FP_MT0;
        const int e0 = (idx & 7) * 64, f0 = (idx >> 3) * 32;
        const int tx = tid & 15, ty = tid >> 4;

        float acc[2][4] = {};
        for (int a0 = 0; a0 < 512; a0 += 64) {
#pragma unroll
            for (int it = 0; it < 2; it++) {
                const int j = tid + it * 256;
                const int r = j >> 4, c4 = j & 15;
                const float4 v = *(const float4*)&p.Wk[(size_t)(f0 + r) * 512 + a0 + c4 * 4];
                As[r][c4*4+0] = v.x; As[r][c4*4+1] = v.y;
                As[r][c4*4+2] = v.z; As[r][c4*4+3] = v.w;
            }
#pragma unroll
            for (int it = 0; it < 4; it++) {
                const int j = tid + it * 256;
                const int r = j >> 4, c4 = j & 15;
                const float4 v = *(const float4*)&p.Wq[(size_t)(e0 + r) * 512 + a0 + c4 * 4];
                Bs[r][c4*4+0] = v.x; Bs[r][c4*4+1] = v.y;
                Bs[r][c4*4+2] = v.z; Bs[r][c4*4+3] = v.w;
            }
            __syncthreads();
#pragma unroll 8
            for (int a = 0; a < 64; a++) {
                const float a0v = As[ty*2][a], a1v = As[ty*2+1][a];
                float b[4];
#pragma unroll
                for (int j = 0; j < 4; j++) b[j] = Bs[tx*4+j][a];
#pragma unroll
                for (int j = 0; j < 4; j++) {
                    acc[0][j] = fmaf(a0v, b[j], acc[0][j]);
                    acc[1][j] = fmaf(a1v, b[j], acc[1][j]);
                }
            }
            __syncthreads();
        }
#pragma unroll
        for (int i = 0; i < 2; i++) {
            const int f = f0 + ty*2 + i;
            __half hi[4], lo[4];
#pragma unroll
            for (int j = 0; j < 4; j++) split_h(acc[i][j], hi[j], lo[j]);
            uint2 hv2, lv2;
            hv2.x = pk2h(hi[0], hi[1]); hv2.y = pk2h(hi[2], hi[3]);
            lv2.x = pk2h(lo[0], lo[1]); lv2.y = pk2h(lo[2], lo[3]);
            *(uint2*)&p.Mh[(size_t)f * 512 + e0 + tx*4] = hv2;
            *(uint2*)&p.Ml[(size_t)f * 512 + e0 + tx*4] = lv2;
        }
    } else if (blk < FP_NT0) {
        // ---- prep_wv: wv[r] = Y[r,:]·hv  (8 rows per block; hv precomputed)
        float* hs = (float*)smbuf;     // 256 floats
        if (tid < 256) hs[tid] = p.hv[tid];
        __syncthreads();
        const int lane = tid & 31;
        const int w = tid >> 5;
        const size_t r = (size_t)(blk - FP_WV0) * 8 + w;
        const float* row = p.Y + r * 256;
        float s = 0.0f;
#pragma unroll
        for (int j = 0; j < 8; j++) s = fmaf(row[lane * 8 + j], hs[lane * 8 + j], s);
#pragma unroll
        for (int o = 16; o; o >>= 1) s += __shfl_xor_sync(0xffffffffu, s, o);
        if (lane == 0) p.wv[r] = s;
    } else if (blk < FP_OB0) {
        // ---- prep_NT: NT[e,f] = Wv[f,:]·Wo[:,e]  (64e x 32f tile)
        float (*Os)[65] = (float(*)[65])smbuf;                    // 64x65
        float (*Vs)[65] = (float(*)[65])(smbuf + 64*65*4);        // 32x65
        const int idx = blk - FP_NT0;
        const int f0 = (idx & 7) * 32, e0 = (idx >> 3) * 64;
        const int tx = tid & 15, ty = tid >> 4;

        float acc[4][2] = {};
        for (int a0 = 0; a0 < 512; a0 += 64) {
#pragma unroll
            for (int it = 0; it < 4; it++) {
                const int j = tid + it * 256;
                const int r = j >> 4, c4 = j & 15;
                const float4 v = *(const float4*)&p.Wo[(size_t)(a0 + r) * 512 + e0 + c4 * 4];
                Os[r][c4*4+0] = v.x; Os[r][c4*4+1] = v.y;
                Os[r][c4*4+2] = v.z; Os[r][c4*4+3] = v.w;
            }
#pragma unroll
            for (int it = 0; it < 2; it++) {
                const int j = tid + it * 256;
                const int r = j >> 4, c4 = j & 15;
                const float4 v = *(const float4*)&p.Wv[(size_t)(f0 + r) * 512 + a0 + c4 * 4];
                Vs[r][c4*4+0] = v.x; Vs[r][c4*4+1] = v.y;
                Vs[r][c4*4+2] = v.z; Vs[r][c4*4+3] = v.w;
            }
            __syncthreads();
#pragma unroll 8
            for (int a = 0; a < 64; a++) {
                float e4[4], fv0, fv1;
#pragma unroll
                for (int i = 0; i < 4; i++) e4[i] = Os[a][ty*4+i];
                fv0 = Vs[tx*2][a]; fv1 = Vs[tx*2+1][a];
#pragma unroll
                for (int i = 0; i < 4; i++) {
                    acc[i][0] = fmaf(e4[i], fv0, acc[i][0]);
                    acc[i][1] = fmaf(e4[i], fv1, acc[i][1]);
                }
            }
            __syncthreads();
        }
#pragma unroll
        for (int i = 0; i < 4; i++) {
            const int e = e0 + ty*4 + i;
            __half hi[2], lo[2];
#pragma unroll
            for (int j = 0; j < 2; j++) split_h(acc[i][j], hi[j], lo[j]);
            *(uint32_t*)&p.Nh[(size_t)e * 256 + f0 + tx*2] = pk2h(hi[0], hi[1]);
            *(uint32_t*)&p.Nl[(size_t)e * 256 + f0 + tx*2] = pk2h(lo[0], lo[1]);
        }
    } else {
        // ---- prep_ob: ob[e] = bo[e] + bv·Wo[:,e]
#pragma unroll
        for (int half = 0; half < 2; half++) {
            const int e = tid + half * 256;
            float s = p.bo[e];
            for (int a = 0; a < 512; a++)
                s = fmaf(p.bv[a], p.Wo[(size_t)a * 512 + e], s);
            p.ob[e] = s;
        }
    }
}

// ---------------------------------------------------------------------------
// Softmax over 2048-col fp32 rows -> hi/lo fp16 row-major
// ---------------------------------------------------------------------------
__global__ __launch_bounds__(256)
void softmax_split(const float* __restrict__ S, __half* __restrict__ Sh,
                   __half* __restrict__ Sl)
{
    const size_t r = blockIdx.x;
    const float* row = S + r * 2048;
    const int tid = threadIdx.x;
    const int c0 = tid * 8;

    float v[8];
    *(float4*)&v[0] = *(const float4*)&row[c0];
    *(float4*)&v[4] = *(const float4*)&row[c0 + 4];

    __shared__ float red[8];
    float m = v[0];
#pragma unroll
    for (int e = 1; e < 8; e++) m = fmaxf(m, v[e]);
#pragma unroll
    for (int o = 16; o; o >>= 1) m = fmaxf(m, __shfl_xor_sync(0xffffffffu, m, o));
    if ((tid & 31) == 0) red[tid >> 5] = m;
    __syncthreads();
    float mx = red[0];
#pragma unroll
    for (int i = 1; i < 8; i++) mx = fmaxf(mx, red[i]);
    __syncthreads();

    float s = 0.0f;
#pragma unroll
    for (int e = 0; e < 8; e++) { v[e] = __expf(v[e] - mx); s += v[e]; }
#pragma unroll
    for (int o = 16; o; o >>= 1) s += __shfl_xor_sync(0xffffffffu, s, o);
    if ((tid & 31) == 0) red[tid >> 5] = s;
    __syncthreads();
    float st = 0.0f;
#pragma unroll
    for (int i = 0; i < 8; i++) st += red[i];
    const float inv = 1.0f / st;

    __half hi[8], lo[8];
#pragma unroll
    for (int e = 0; e < 8; e++) split_h(v[e] * inv, hi[e], lo[e]);
    uint4 hv4, lv4;
    hv4.x = pk2h(hi[0],hi[1]); hv4.y = pk2h(hi[2],hi[3]);
    hv4.z = pk2h(hi[4],hi[5]); hv4.w = pk2h(hi[6],hi[7]);
    lv4.x = pk2h(lo[0],lo[1]); lv4.y = pk2h(lo[2],lo[3]);
    lv4.z = pk2h(lo[4],lo[5]); lv4.w = pk2h(lo[6],lo[7]);
    *(uint4*)&Sh[r * 2048 + c0] = hv4;
    *(uint4*)&Sl[r * 2048 + c0] = lv4;
}

// ---------------------------------------------------------------------------
// Launch
// ---------------------------------------------------------------------------
extern "C" void kernel_launch(void* const* d_in, const int* in_sizes, int n_in,
                              void* d_out, int out_size)
{
    const float* X  = (const float*)d_in[0];
    const float* Y  = (const float*)d_in[1];
    const float* Wq = (const float*)d_in[2];
    const float* bq = (const float*)d_in[3];
    const float* Wk = (const float*)d_in[4];
    const float* Wv = (const float*)d_in[6];
    const float* bv = (const float*)d_in[7];
    const float* Wo = (const float*)d_in[8];
    const float* bo = (const float*)d_in[9];
    float* out = (float*)d_out;

    constexpr int SMEM3 = STAGES * (2 * A_TILE_B + 2 * B_TILE_B);   // 184320
    constexpr int SMEM2 = STAGES * (2 * A_TILE_B + 1 * B_TILE_B);   // 122880
    cudaFuncSetAttribute(gemm_mma<3,0,1>, cudaFuncAttributeMaxDynamicSharedMemorySize, SMEM3);
    cudaFuncSetAttribute(gemm_mma<3,1,0>, cudaFuncAttributeMaxDynamicSharedMemorySize, SMEM3);
    cudaFuncSetAttribute(gemm_mma<2,1,0>, cudaFuncAttributeMaxDynamicSharedMemorySize, SMEM2);
    cudaFuncSetAttribute(gemm_mma<2,0,1>, cudaFuncAttributeMaxDynamicSharedMemorySize, SMEM2);

    __half *Xh,*Xl,*Yh,*Yl,*YTh,*YTl,*Mh,*Ml,*Nh,*Nl,*Th,*Tl,*Ph,*Pl,*Ch,*Cl;
    float *S,*hv,*wv,*ob;
    cudaGetSymbolAddress((void**)&Xh, g_Xh);   cudaGetSymbolAddress((void**)&Xl, g_Xl);
    cudaGetSymbolAddress((void**)&Yh, g_Yh);   cudaGetSymbolAddress((void**)&Yl, g_Yl);
    cudaGetSymbolAddress((void**)&YTh, g_YTh); cudaGetSymbolAddress((void**)&YTl, g_YTl);
    cudaGetSymbolAddress((void**)&Mh, g_Mh);   cudaGetSymbolAddress((void**)&Ml, g_Ml);
    cudaGetSymbolAddress((void**)&Nh, g_Nh);   cudaGetSymbolAddress((void**)&Nl, g_Nl);
    cudaGetSymbolAddress((void**)&Th, g_Th);   cudaGetSymbolAddress((void**)&Tl, g_Tl);
    cudaGetSymbolAddress((void**)&Ph, g_Ph);   cudaGetSymbolAddress((void**)&Pl, g_Pl);
    cudaGetSymbolAddress((void**)&Ch, g_Ch);   cudaGetSymbolAddress((void**)&Cl, g_Cl);
    cudaGetSymbolAddress((void**)&S, g_S);
    cudaGetSymbolAddress((void**)&hv, g_hv);
    cudaGetSymbolAddress((void**)&wv, g_wv);
    cudaGetSymbolAddress((void**)&ob, g_ob);

    // 1: hv (feeds wv inside fused prep)
    prep_hv<<<1, 256>>>(Wk, bq, hv);
    // 2: fused prep (everything independent, one launch)
    {
        PrepArgs p{X, Y, Wq, Wk, Wv, Wo, bv, bo, hv,
                   Xh, Xl, Yh, Yl, YTh, YTl, Mh, Ml, Nh, Nl,
                   wv, ob};
        fused_prep<<<FP_NBLK, 256>>>(p);
    }
    // 3: T = X @ M -> split [16384,256]   (3-term)
    {
        GemmArgs a{Xh, Xl, Mh, Ml, nullptr, nullptr, Th, Tl,
                   512, 0, 0, 0, 256, 0};
        gemm_mma<3,1,0><<<dim3(1,128,1), 512, SMEM3>>>(a);
    }
    // 4: S = T_z @ Y_z^T + wv -> fp32 [1024,2048] x16   (3-term)
    {
        GemmArgs a{Th, Tl, Yh, Yl, wv, S, nullptr, nullptr,
                   256, (long long)1024*256, (long long)2048*256,
                   (long long)1024*2048, 2048, 2048};
        gemm_mma<3,0,1><<<dim3(8,8,16), 512, SMEM3>>>(a);
    }
    // 5: softmax -> P split
    softmax_split<<<16384, 256>>>(S, Ph, Pl);
    // 6: C = (Ph+Pl) @ Yh -> split [1024,256] x16   (2-term)
    {
        GemmArgs a{Ph, Pl, YTh, nullptr, nullptr, nullptr, Ch, Cl,
                   2048, (long long)1024*2048, (long long)256*2048,
                   (long long)1024*256, 256, 0};
        gemm_mma<2,1,0><<<dim3(1,8,16), 512, SMEM2>>>(a);
    }
    // 7: out = (Ch+Cl) @ Nh + ob -> fp32 [16384,512]   (2-term)
    {
        GemmArgs a{Ch, Cl, Nh, nullptr, ob, out, nullptr, nullptr,
                   256, 0, 0, 0, 512, 0};
        gemm_mma<2,0,1><<<dim3(2,128,1), 512, SMEM2>>>(a);
    }
}

// round 15
// speedup vs baseline: 1.9686x; 1.0908x over previous
#include <cuda_runtime.h>
#include <cuda_fp16.h>
#include <cstdint>
#include <cstddef>

// ---------------------------------------------------------------------------
// CrossAttention on sm_100 via mma.sync fp16 (HMMA), split fp32 accum.
// R15: C = Ph@Yh (1-term; softmax one-hot error budget) and softmax writes
// only Ph. Rest identical to R14.
//   S = X(WqWk^T)Y^T + wv ;  out = (P@Y)@(WvWo) + (bv·Wo+bo)
// ---------------------------------------------------------------------------

#define STAGES 3
#define BK 32
#define TROW 80                     // padded smem row bytes (40 fp16)
#define A_TILE_B (128 * TROW)       // 10240
#define B_TILE_B (256 * TROW)       // 20480

// ---------------- scratch (device globals) ---------------------------------
__device__ __half g_Xh[(size_t)16384*512],  g_Xl[(size_t)16384*512];
__device__ __half g_Yh[(size_t)32768*256],  g_Yl[(size_t)32768*256];
__device__ __half g_YTh[(size_t)16*256*2048], g_YTl[(size_t)16*256*2048];
__device__ __half g_Mh[256*512],  g_Ml[256*512];    // (WqWk^T)^T : [256f, 512e]
__device__ __half g_Nh[512*256],  g_Nl[512*256];    // (WvWo)^T   : [512e, 256f]
__device__ __half g_Th[(size_t)16384*256],  g_Tl[(size_t)16384*256];
__device__ float  g_S[(size_t)16*1024*2048];
__device__ __half g_Ph[(size_t)16384*2048];
__device__ __half g_Ch[(size_t)16384*256],  g_Cl[(size_t)16384*256];
__device__ float  g_hv[256];       // Wk @ bq
__device__ float  g_wv[32768];     // Y @ (Wk @ bq)  (per-key logit bias)
__device__ float  g_ob[512];       // bv @ Wo + bo

// ---------------- helpers ---------------------------------------------------
__device__ __forceinline__ uint32_t smem_u32(const void* p) {
    uint32_t a;
    asm("{ .reg .u64 t; cvta.to.shared.u64 t, %1; cvt.u32.u64 %0, t; }"
        : "=r"(a) : "l"(p));
    return a;
}
__device__ __forceinline__ void cp16(uint32_t dst, const void* src) {
    asm volatile("cp.async.cg.shared.global [%0], [%1], 16;"
                 :: "r"(dst), "l"(src) : "memory");
}
__device__ __forceinline__ void cp_commit() {
    asm volatile("cp.async.commit_group;" ::: "memory");
}
__device__ __forceinline__ void cp_wait1() {
    asm volatile("cp.async.wait_group 1;" ::: "memory");
}
__device__ __forceinline__ void ldm4(uint32_t* r, uint32_t addr) {
    asm volatile("ldmatrix.sync.aligned.m8n8.x4.shared.b16 {%0,%1,%2,%3}, [%4];"
                 : "=r"(r[0]), "=r"(r[1]), "=r"(r[2]), "=r"(r[3]) : "r"(addr));
}
__device__ __forceinline__ void mma16816(float* d, const uint32_t* a,
                                         uint32_t b0, uint32_t b1) {
    asm volatile(
        "mma.sync.aligned.m16n8k16.row.col.f32.f16.f16.f32 "
        "{%0,%1,%2,%3}, {%4,%5,%6,%7}, {%8,%9}, {%0,%1,%2,%3};"
        : "+f"(d[0]), "+f"(d[1]), "+f"(d[2]), "+f"(d[3])
        : "r"(a[0]), "r"(a[1]), "r"(a[2]), "r"(a[3]), "r"(b0), "r"(b1));
}
__device__ __forceinline__ uint32_t pk2h(__half a, __half b) {
    return ((uint32_t)__half_as_ushort(b) << 16) | (uint32_t)__half_as_ushort(a);
}
__device__ __forceinline__ void split_h(float x, __half& hi, __half& lo) {
    hi = __float2half(x);
    lo = __float2half(x - __half2float(hi));
}

// ---------------------------------------------------------------------------
// Split-fp16 GEMM. A:[Mtot,K], B:[Ntot,K] row-major hi/lo.
// TERMS=3: AhBh+AlBh+AhBl.  TERMS=2: AhBh+AlBh.  TERMS=1: AhBh only.
// Tile 128x256, BK=32, 3-stage cp.async, 16 warps (4Mx4N).
// EPI: 0 = fp32 out, 1 = split-fp16 out. BIAS: 0 none, 1 per-n (z-strided).
// ---------------------------------------------------------------------------
struct GemmArgs {
    const __half *Ah, *Al, *Bh, *Bl;
    const float* bias;
    float* outF;
    __half *outH, *outL;
    int K;
    long long aZ, bZ, outZ;
    int ldc;
    int biasZ;
};

template <int TERMS, int EPI, int BIAS>
__global__ __launch_bounds__(512, 1)
void gemm_mma(GemmArgs g)
{
    constexpr int NA = (TERMS >= 2) ? 2 : 1;               // A tiles (Ah[,Al])
    constexpr int OFF_AH = 0;
    constexpr int OFF_AL = A_TILE_B;                       // valid iff NA==2
    constexpr int OFF_BH = NA * A_TILE_B;
    constexpr int OFF_BL = NA * A_TILE_B + B_TILE_B;       // TERMS==3 only
    constexpr int STAGE_B = NA * A_TILE_B + (TERMS == 3 ? 2 : 1) * B_TILE_B;

    extern __shared__ char smem[];
    const uint32_t sm0 = smem_u32(smem);
    const int tid = threadIdx.x, lane = tid & 31, wid = tid >> 5;
    const int wm = wid & 3, wn = wid >> 2;
    const int z = blockIdx.z;
    const int m0 = blockIdx.y * 128, n0 = blockIdx.x * 256;
    const int K = g.K, nkt = K / BK;

    const __half* sAh = g.Ah + (size_t)z * g.aZ + (size_t)m0 * K;
    const __half* sAl = (TERMS >= 2) ? g.Al + (size_t)z * g.aZ + (size_t)m0 * K : nullptr;
    const __half* sBh = g.Bh + (size_t)z * g.bZ + (size_t)n0 * K;
    const __half* sBl = (TERMS == 3) ? g.Bl + (size_t)z * g.bZ + (size_t)n0 * K : nullptr;
    const float* bp = (BIAS == 1) ? (g.bias + (size_t)z * g.biasZ) : nullptr;

    const int lr = tid >> 2, lc = tid & 3;

    float acc[2][8][4];
#pragma unroll
    for (int i = 0; i < 2; i++)
#pragma unroll
        for (int j = 0; j < 8; j++)
#pragma unroll
            for (int e = 0; e < 4; e++) acc[i][j][e] = 0.0f;

    const uint32_t aoff = (uint32_t)(wm * 32 + (lane & 7) + ((lane >> 3) & 1) * 8) * TROW
                        + (lane >> 4) * 16;
    const uint32_t boff = (uint32_t)(wn * 64 + (lane & 7) + ((lane >> 4) & 1) * 8) * TROW
                        + ((lane >> 3) & 1) * 16;

    auto load_stage = [&](int kt, int s) {
        const uint32_t stb = sm0 + s * STAGE_B;
        const size_t kofs = (size_t)kt * BK;
        const uint32_t drow = (uint32_t)lr * TROW + lc * 16;
        const size_t srow = (size_t)lr * K + kofs + lc * 8;
        cp16(stb + OFF_AH + drow, sAh + srow);
        if (TERMS >= 2) cp16(stb + OFF_AL + drow, sAl + srow);
#pragma unroll
        for (int h = 0; h < 2; h++) {
            const uint32_t r = lr + h * 128;
            const uint32_t d2 = (uint32_t)r * TROW + lc * 16;
            const size_t s2 = (size_t)r * K + kofs + lc * 8;
            cp16(stb + OFF_BH + d2, sBh + s2);
            if (TERMS == 3) cp16(stb + OFF_BL + d2, sBl + s2);
        }
    };

    auto compute_stage = [&](int s) {
        const uint32_t stb = sm0 + s * STAGE_B;
#pragma unroll
        for (int ks = 0; ks < 2; ks++) {
            uint32_t aH[2][4], aL[2][4], bB[4][4];
#pragma unroll
            for (int mt = 0; mt < 2; mt++) {
                const uint32_t o = aoff + (uint32_t)mt * 16 * TROW + ks * 32;
                ldm4(aH[mt], stb + OFF_AH + o);
                if (TERMS >= 2) ldm4(aL[mt], stb + OFF_AL + o);
            }
#pragma unroll
            for (int np = 0; np < 4; np++)
                ldm4(bB[np], stb + OFF_BH + boff + (uint32_t)np * 16 * TROW + ks * 32);
            // Ah @ Bh
#pragma unroll
            for (int mt = 0; mt < 2; mt++)
#pragma unroll
                for (int nt = 0; nt < 8; nt++) {
                    const uint32_t* b = &bB[nt >> 1][(nt & 1) * 2];
                    mma16816(acc[mt][nt], aH[mt], b[0], b[1]);
                }
            // Al @ Bh
            if (TERMS >= 2) {
#pragma unroll
                for (int mt = 0; mt < 2; mt++)
#pragma unroll
                    for (int nt = 0; nt < 8; nt++) {
                        const uint32_t* b = &bB[nt >> 1][(nt & 1) * 2];
                        mma16816(acc[mt][nt], aL[mt], b[0], b[1]);
                    }
            }
            if (TERMS == 3) {
#pragma unroll
                for (int np = 0; np < 4; np++)
                    ldm4(bB[np], stb + OFF_BL + boff + (uint32_t)np * 16 * TROW + ks * 32);
#pragma unroll
                for (int mt = 0; mt < 2; mt++)
#pragma unroll
                    for (int nt = 0; nt < 8; nt++) {
                        const uint32_t* b = &bB[nt >> 1][(nt & 1) * 2];
                        mma16816(acc[mt][nt], aH[mt], b[0], b[1]);
                    }
            }
        }
    };

#pragma unroll
    for (int s = 0; s < STAGES - 1; s++) { load_stage(s, s); cp_commit(); }
    for (int kt = 0; kt < nkt; kt++) {
        cp_wait1();
        __syncthreads();
        const int nx = kt + STAGES - 1;
        if (nx < nkt) load_stage(nx, nx % STAGES);
        cp_commit();
        compute_stage(kt % STAGES);
    }

    // ---------------- epilogue --------------------------------------------
    const int rr = lane >> 2, rc = (lane & 3) * 2;
#pragma unroll
    for (int mt = 0; mt < 2; mt++) {
#pragma unroll
        for (int nt = 0; nt < 8; nt++) {
            float* d = acc[mt][nt];
            const int m = m0 + wm * 32 + mt * 16 + rr;
            const int n = n0 + wn * 64 + nt * 8 + rc;
            float v[4] = {d[0], d[1], d[2], d[3]};
            if (BIAS == 1) {
                const float b0v = bp[n], b1v = bp[n + 1];
                v[0] += b0v; v[1] += b1v; v[2] += b0v; v[3] += b1v;
            }
            if (EPI == 0) {
                float* o = g.outF + (size_t)z * g.outZ;
                *(float2*)&o[(size_t)m * g.ldc + n]       = make_float2(v[0], v[1]);
                *(float2*)&o[(size_t)(m + 8) * g.ldc + n] = make_float2(v[2], v[3]);
            } else {
                __half hi[4], lo[4];
#pragma unroll
                for (int e = 0; e < 4; e++) split_h(v[e], hi[e], lo[e]);
                __half* oh = g.outH + (size_t)z * g.outZ;
                __half* ol = g.outL + (size_t)z * g.outZ;
                *(uint32_t*)&oh[(size_t)m * g.ldc + n]       = pk2h(hi[0], hi[1]);
                *(uint32_t*)&oh[(size_t)(m + 8) * g.ldc + n] = pk2h(hi[2], hi[3]);
                *(uint32_t*)&ol[(size_t)m * g.ldc + n]       = pk2h(lo[0], lo[1]);
                *(uint32_t*)&ol[(size_t)(m + 8) * g.ldc + n] = pk2h(lo[2], lo[3]);
            }
        }
    }
}

// ---------------------------------------------------------------------------
// prep_hv: hv[f] = Wk[f,:] . bq  (single block; launched before fused prep)
// ---------------------------------------------------------------------------
__global__ __launch_bounds__(256)
void prep_hv(const float* __restrict__ Wk, const float* __restrict__ bq,
             float* __restrict__ hv)
{
    const int f = threadIdx.x;
    float s = 0.0f;
    for (int a = 0; a < 512; a++) s = fmaf(Wk[(size_t)f * 512 + a], bq[a], s);
    hv[f] = s;
}

// ---------------------------------------------------------------------------
// Fused prep mega-kernel: blockIdx.x ranges dispatch independent jobs.
// ---------------------------------------------------------------------------
#define FP_SPLITX0   0
#define FP_SPLITY0   4096
#define FP_TRANS0    8192
#define FP_MT0       10240
#define FP_WV0       10304
#define FP_NT0       14400
#define FP_OB0       14464
#define FP_NBLK      14465

struct PrepArgs {
    const float *X, *Y, *Wq, *Wk, *Wv, *Wo, *bv, *bo, *hv;
    __half *Xh, *Xl, *Yh, *Yl, *YTh, *YTl, *Mh, *Ml, *Nh, *Nl;
    float *wv, *ob;
};

__global__ __launch_bounds__(256)
void fused_prep(PrepArgs p)
{
    __shared__ __align__(16) char smbuf[24960];
    const int blk = blockIdx.x;
    const int tid = threadIdx.x;

    if (blk < FP_SPLITY0) {
        // ---- splitX
        const size_t id = (size_t)(blk - FP_SPLITX0) * 256 + tid;
        float v[8];
        *(float4*)&v[0] = ((const float4*)p.X)[id * 2];
        *(float4*)&v[4] = ((const float4*)p.X)[id * 2 + 1];
        __half hi[8], lo[8];
#pragma unroll
        for (int e = 0; e < 8; e++) split_h(v[e], hi[e], lo[e]);
        uint4 hv4, lv4;
        hv4.x = pk2h(hi[0],hi[1]); hv4.y = pk2h(hi[2],hi[3]);
        hv4.z = pk2h(hi[4],hi[5]); hv4.w = pk2h(hi[6],hi[7]);
        lv4.x = pk2h(lo[0],lo[1]); lv4.y = pk2h(lo[2],lo[3]);
        lv4.z = pk2h(lo[4],lo[5]); lv4.w = pk2h(lo[6],lo[7]);
        *(uint4*)&p.Xh[id * 8] = hv4;
        *(uint4*)&p.Xl[id * 8] = lv4;
    } else if (blk < FP_TRANS0) {
        // ---- splitY
        const size_t id = (size_t)(blk - FP_SPLITY0) * 256 + tid;
        float v[8];
        *(float4*)&v[0] = ((const float4*)p.Y)[id * 2];
        *(float4*)&v[4] = ((const float4*)p.Y)[id * 2 + 1];
        __half hi[8], lo[8];
#pragma unroll
        for (int e = 0; e < 8; e++) split_h(v[e], hi[e], lo[e]);
        uint4 hv4, lv4;
        hv4.x = pk2h(hi[0],hi[1]); hv4.y = pk2h(hi[2],hi[3]);
        hv4.z = pk2h(hi[4],hi[5]); hv4.w = pk2h(hi[6],hi[7]);
        lv4.x = pk2h(lo[0],lo[1]); lv4.y = pk2h(lo[2],lo[3]);
        lv4.z = pk2h(lo[4],lo[5]); lv4.w = pk2h(lo[6],lo[7]);
        *(uint4*)&p.Yh[id * 8] = hv4;
        *(uint4*)&p.Yl[id * 8] = lv4;
    } else if (blk < FP_MT0) {
        // ---- transpose_split: Y [2048,256] -> Y^T split [256,2048] x16
        float (*t)[65] = (float(*)[65])smbuf;
        const int idx = blk - FP_TRANS0;
        const int z  = idx >> 7;
        const int r7 = idx & 127;
        const int k0 = (r7 >> 2) * 64;
        const int f0 = (r7 & 3) * 64;
        const float* Yb = p.Y + (size_t)z * 2048 * 256;

        for (int i = tid; i < 64 * 16; i += 256) {
            const int r = i >> 4, c4 = i & 15;
            const float4 v = *(const float4*)&Yb[(size_t)(k0 + r) * 256 + f0 + c4 * 4];
            t[r][c4 * 4 + 0] = v.x; t[r][c4 * 4 + 1] = v.y;
            t[r][c4 * 4 + 2] = v.z; t[r][c4 * 4 + 3] = v.w;
        }
        __syncthreads();
        __half* thb = p.YTh + (size_t)z * 256 * 2048;
        __half* tlb = p.YTl + (size_t)z * 256 * 2048;
        for (int i = tid; i < 64 * 16; i += 256) {
            const int f = i >> 4, c4 = i & 15;
            __half hi[4], lo[4];
#pragma unroll
            for (int e = 0; e < 4; e++) split_h(t[c4 * 4 + e][f], hi[e], lo[e]);
            uint2 hv2, lv2;
            hv2.x = pk2h(hi[0], hi[1]); hv2.y = pk2h(hi[2], hi[3]);
            lv2.x = pk2h(lo[0], lo[1]); lv2.y = pk2h(lo[2], lo[3]);
            *(uint2*)&thb[(size_t)(f0 + f) * 2048 + k0 + c4 * 4] = hv2;
            *(uint2*)&tlb[(size_t)(f0 + f) * 2048 + k0 + c4 * 4] = lv2;
        }
    } else if (blk < FP_WV0) {
        // ---- prep_MT: MT[f,e] = Wk[f,:]·Wq[e,:]  (32f x 64e tile)
        float (*As)[65] = (float(*)[65])smbuf;
        float (*Bs)[65] = (float(*)[65])(smbuf + 32*65*4);
        const int idx = blk - FP_MT0;
        const int e0 = (idx & 7) * 64, f0 = (idx >> 3) * 32;
        const int tx = tid & 15, ty = tid >> 4;

        float acc[2][4] = {};
        for (int a0 = 0; a0 < 512; a0 += 64) {
#pragma unroll
            for (int it = 0; it < 2; it++) {
                const int j = tid + it * 256;
                const int r = j >> 4, c4 = j & 15;
                const float4 v = *(const float4*)&p.Wk[(size_t)(f0 + r) * 512 + a0 + c4 * 4];
                As[r][c4*4+0] = v.x; As[r][c4*4+1] = v.y;
                As[r][c4*4+2] = v.z; As[r][c4*4+3] = v.w;
            }
#pragma unroll
            for (int it = 0; it < 4; it++) {
                const int j = tid + it * 256;
                const int r = j >> 4, c4 = j & 15;
                const float4 v = *(const float4*)&p.Wq[(size_t)(e0 + r) * 512 + a0 + c4 * 4];
                Bs[r][c4*4+0] = v.x; Bs[r][c4*4+1] = v.y;
                Bs[r][c4*4+2] = v.z; Bs[r][c4*4+3] = v.w;
            }
            __syncthreads();
#pragma unroll 8
            for (int a = 0; a < 64; a++) {
                const float a0v = As[ty*2][a], a1v = As[ty*2+1][a];
                float b[4];
#pragma unroll
                for (int j = 0; j < 4; j++) b[j] = Bs[tx*4+j][a];
#pragma unroll
                for (int j = 0; j < 4; j++) {
                    acc[0][j] = fmaf(a0v, b[j], acc[0][j]);
                    acc[1][j] = fmaf(a1v, b[j], acc[1][j]);
                }
            }
            __syncthreads();
        }
#pragma unroll
        for (int i = 0; i < 2; i++) {
            const int f = f0 + ty*2 + i;
            __half hi[4], lo[4];
#pragma unroll
            for (int j = 0; j < 4; j++) split_h(acc[i][j], hi[j], lo[j]);
            uint2 hv2, lv2;
            hv2.x = pk2h(hi[0], hi[1]); hv2.y = pk2h(hi[2], hi[3]);
            lv2.x = pk2h(lo[0], lo[1]); lv2.y = pk2h(lo[2], lo[3]);
            *(uint2*)&p.Mh[(size_t)f * 512 + e0 + tx*4] = hv2;
            *(uint2*)&p.Ml[(size_t)f * 512 + e0 + tx*4] = lv2;
        }
    } else if (blk < FP_NT0) {
        // ---- prep_wv: wv[r] = Y[r,:]·hv  (8 rows per block; hv precomputed)
        float* hs = (float*)smbuf;
        if (tid < 256) hs[tid] = p.hv[tid];
        __syncthreads();
        const int lane = tid & 31;
        const int w = tid >> 5;
        const size_t r = (size_t)(blk - FP_WV0) * 8 + w;
        const float* row = p.Y + r * 256;
        float s = 0.0f;
#pragma unroll
        for (int j = 0; j < 8; j++) s = fmaf(row[lane * 8 + j], hs[lane * 8 + j], s);
#pragma unroll
        for (int o = 16; o; o >>= 1) s += __shfl_xor_sync(0xffffffffu, s, o);
        if (lane == 0) p.wv[r] = s;
    } else if (blk < FP_OB0) {
        // ---- prep_NT: NT[e,f] = Wv[f,:]·Wo[:,e]  (64e x 32f tile)
        float (*Os)[65] = (float(*)[65])smbuf;
        float (*Vs)[65] = (float(*)[65])(smbuf + 64*65*4);
        const int idx = blk - FP_NT0;
        const int f0 = (idx & 7) * 32, e0 = (idx >> 3) * 64;
        const int tx = tid & 15, ty = tid >> 4;

        float acc[4][2] = {};
        for (int a0 = 0; a0 < 512; a0 += 64) {
#pragma unroll
            for (int it = 0; it < 4; it++) {
                const int j = tid + it * 256;
                const int r = j >> 4, c4 = j & 15;
                const float4 v = *(const float4*)&p.Wo[(size_t)(a0 + r) * 512 + e0 + c4 * 4];
                Os[r][c4*4+0] = v.x; Os[r][c4*4+1] = v.y;
                Os[r][c4*4+2] = v.z; Os[r][c4*4+3] = v.w;
            }
#pragma unroll
            for (int it = 0; it < 2; it++) {
                const int j = tid + it * 256;
                const int r = j >> 4, c4 = j & 15;
                const float4 v = *(const float4*)&p.Wv[(size_t)(f0 + r) * 512 + a0 + c4 * 4];
                Vs[r][c4*4+0] = v.x; Vs[r][c4*4+1] = v.y;
                Vs[r][c4*4+2] = v.z; Vs[r][c4*4+3] = v.w;
            }
            __syncthreads();
#pragma unroll 8
            for (int a = 0; a < 64; a++) {
                float e4[4], fv0, fv1;
#pragma unroll
                for (int i = 0; i < 4; i++) e4[i] = Os[a][ty*4+i];
                fv0 = Vs[tx*2][a]; fv1 = Vs[tx*2+1][a];
#pragma unroll
                for (int i = 0; i < 4; i++) {
                    acc[i][0] = fmaf(e4[i], fv0, acc[i][0]);
                    acc[i][1] = fmaf(e4[i], fv1, acc[i][1]);
                }
            }
            __syncthreads();
        }
#pragma unroll
        for (int i = 0; i < 4; i++) {
            const int e = e0 + ty*4 + i;
            __half hi[2], lo[2];
#pragma unroll
            for (int j = 0; j < 2; j++) split_h(acc[i][j], hi[j], lo[j]);
            *(uint32_t*)&p.Nh[(size_t)e * 256 + f0 + tx*2] = pk2h(hi[0], hi[1]);
            *(uint32_t*)&p.Nl[(size_t)e * 256 + f0 + tx*2] = pk2h(lo[0], lo[1]);
        }
    } else {
        // ---- prep_ob: ob[e] = bo[e] + bv·Wo[:,e]
#pragma unroll
        for (int half = 0; half < 2; half++) {
            const int e = tid + half * 256;
            float s = p.bo[e];
            for (int a = 0; a < 512; a++)
                s = fmaf(p.bv[a], p.Wo[(size_t)a * 512 + e], s);
            p.ob[e] = s;
        }
    }
}

// ---------------------------------------------------------------------------
// Softmax over 2048-col fp32 rows -> fp16 (hi only; Pl unused downstream)
// ---------------------------------------------------------------------------
__global__ __launch_bounds__(256)
void softmax_h(const float* __restrict__ S, __half* __restrict__ Sh)
{
    const size_t r = blockIdx.x;
    const float* row = S + r * 2048;
    const int tid = threadIdx.x;
    const int c0 = tid * 8;

    float v[8];
    *(float4*)&v[0] = *(const float4*)&row[c0];
    *(float4*)&v[4] = *(const float4*)&row[c0 + 4];

    __shared__ float red[8];
    float m = v[0];
#pragma unroll
    for (int e = 1; e < 8; e++) m = fmaxf(m, v[e]);
#pragma unroll
    for (int o = 16; o; o >>= 1) m = fmaxf(m, __shfl_xor_sync(0xffffffffu, m, o));
    if ((tid & 31) == 0) red[tid >> 5] = m;
    __syncthreads();
    float mx = red[0];
#pragma unroll
    for (int i = 1; i < 8; i++) mx = fmaxf(mx, red[i]);
    __syncthreads();

    float s = 0.0f;
#pragma unroll
    for (int e = 0; e < 8; e++) { v[e] = __expf(v[e] - mx); s += v[e]; }
#pragma unroll
    for (int o = 16; o; o >>= 1) s += __shfl_xor_sync(0xffffffffu, s, o);
    if ((tid & 31) == 0) red[tid >> 5] = s;
    __syncthreads();
    float st = 0.0f;
#pragma unroll
    for (int i = 0; i < 8; i++) st += red[i];
    const float inv = 1.0f / st;

    __half hi[8];
#pragma unroll
    for (int e = 0; e < 8; e++) hi[e] = __float2half(v[e] * inv);
    uint4 hv4;
    hv4.x = pk2h(hi[0],hi[1]); hv4.y = pk2h(hi[2],hi[3]);
    hv4.z = pk2h(hi[4],hi[5]); hv4.w = pk2h(hi[6],hi[7]);
    *(uint4*)&Sh[r * 2048 + c0] = hv4;
}

// ---------------------------------------------------------------------------
// Launch
// ---------------------------------------------------------------------------
extern "C" void kernel_launch(void* const* d_in, const int* in_sizes, int n_in,
                              void* d_out, int out_size)
{
    const float* X  = (const float*)d_in[0];
    const float* Y  = (const float*)d_in[1];
    const float* Wq = (const float*)d_in[2];
    const float* bq = (const float*)d_in[3];
    const float* Wk = (const float*)d_in[4];
    const float* Wv = (const float*)d_in[6];
    const float* bv = (const float*)d_in[7];
    const float* Wo = (const float*)d_in[8];
    const float* bo = (const float*)d_in[9];
    float* out = (float*)d_out;

    constexpr int SMEM3 = STAGES * (2 * A_TILE_B + 2 * B_TILE_B);   // 184320
    constexpr int SMEM2 = STAGES * (2 * A_TILE_B + 1 * B_TILE_B);   // 122880
    constexpr int SMEM1 = STAGES * (1 * A_TILE_B + 1 * B_TILE_B);   // 92160
    cudaFuncSetAttribute(gemm_mma<3,0,1>, cudaFuncAttributeMaxDynamicSharedMemorySize, SMEM3);
    cudaFuncSetAttribute(gemm_mma<3,1,0>, cudaFuncAttributeMaxDynamicSharedMemorySize, SMEM3);
    cudaFuncSetAttribute(gemm_mma<1,1,0>, cudaFuncAttributeMaxDynamicSharedMemorySize, SMEM1);
    cudaFuncSetAttribute(gemm_mma<2,0,1>, cudaFuncAttributeMaxDynamicSharedMemorySize, SMEM2);

    __half *Xh,*Xl,*Yh,*Yl,*YTh,*YTl,*Mh,*Ml,*Nh,*Nl,*Th,*Tl,*Ph,*Ch,*Cl;
    float *S,*hv,*wv,*ob;
    cudaGetSymbolAddress((void**)&Xh, g_Xh);   cudaGetSymbolAddress((void**)&Xl, g_Xl);
    cudaGetSymbolAddress((void**)&Yh, g_Yh);   cudaGetSymbolAddress((void**)&Yl, g_Yl);
    cudaGetSymbolAddress((void**)&YTh, g_YTh); cudaGetSymbolAddress((void**)&YTl, g_YTl);
    cudaGetSymbolAddress((void**)&Mh, g_Mh);   cudaGetSymbolAddress((void**)&Ml, g_Ml);
    cudaGetSymbolAddress((void**)&Nh, g_Nh);   cudaGetSymbolAddress((void**)&Nl, g_Nl);
    cudaGetSymbolAddress((void**)&Th, g_Th);   cudaGetSymbolAddress((void**)&Tl, g_Tl);
    cudaGetSymbolAddress((void**)&Ph, g_Ph);
    cudaGetSymbolAddress((void**)&Ch, g_Ch);   cudaGetSymbolAddress((void**)&Cl, g_Cl);
    cudaGetSymbolAddress((void**)&S, g_S);
    cudaGetSymbolAddress((void**)&hv, g_hv);
    cudaGetSymbolAddress((void**)&wv, g_wv);
    cudaGetSymbolAddress((void**)&ob, g_ob);

    // 1: hv (feeds wv inside fused prep)
    prep_hv<<<1, 256>>>(Wk, bq, hv);
    // 2: fused prep (everything independent, one launch)
    {
        PrepArgs p{X, Y, Wq, Wk, Wv, Wo, bv, bo, hv,
                   Xh, Xl, Yh, Yl, YTh, YTl, Mh, Ml, Nh, Nl,
                   wv, ob};
        fused_prep<<<FP_NBLK, 256>>>(p);
    }
    // 3: T = X @ M -> split [16384,256]   (3-term)
    {
        GemmArgs a{Xh, Xl, Mh, Ml, nullptr, nullptr, Th, Tl,
                   512, 0, 0, 0, 256, 0};
        gemm_mma<3,1,0><<<dim3(1,128,1), 512, SMEM3>>>(a);
    }
    // 4: S = T_z @ Y_z^T + wv -> fp32 [1024,2048] x16   (3-term)
    {
        GemmArgs a{Th, Tl, Yh, Yl, wv, S, nullptr, nullptr,
                   256, (long long)1024*256, (long long)2048*256,
                   (long long)1024*2048, 2048, 2048};
        gemm_mma<3,0,1><<<dim3(8,8,16), 512, SMEM3>>>(a);
    }
    // 5: softmax -> Ph (hi only)
    softmax_h<<<16384, 256>>>(S, Ph);
    // 6: C = Ph @ Yh -> split [1024,256] x16   (1-term)
    {
        GemmArgs a{Ph, nullptr, YTh, nullptr, nullptr, nullptr, Ch, Cl,
                   2048, (long long)1024*2048, (long long)256*2048,
                   (long long)1024*256, 256, 0};
        gemm_mma<1,1,0><<<dim3(1,8,16), 512, SMEM1>>>(a);
    }
    // 7: out = (Ch+Cl) @ Nh + ob -> fp32 [16384,512]   (2-term)
    {
        GemmArgs a{Ch, Cl, Nh, nullptr, ob, out, nullptr, nullptr,
                   256, 0, 0, 0, 512, 0};
        gemm_mma<2,0,1><<<dim3(2,128,1), 512, SMEM2>>>(a);
    }
}

// round 16
// speedup vs baseline: 1.9754x; 1.0034x over previous
#include <cuda_runtime.h>
#include <cuda_fp16.h>
#include <cstdint>
#include <cstddef>

// ---------------------------------------------------------------------------
// CrossAttention on sm_100 via mma.sync fp16 (HMMA), split fp32 accum.
// R16: R15 + Programmatic Dependent Launch on all kernels (overlap launch
// latency and wave ramps across the 7-kernel chain). No numerical change.
//   S = X(WqWk^T)Y^T + wv ;  out = (P@Y)@(WvWo) + (bv·Wo+bo)
// ---------------------------------------------------------------------------

#define STAGES 3
#define BK 32
#define TROW 80                     // padded smem row bytes (40 fp16)
#define A_TILE_B (128 * TROW)       // 10240
#define B_TILE_B (256 * TROW)       // 20480

// ---------------- scratch (device globals) ---------------------------------
__device__ __half g_Xh[(size_t)16384*512],  g_Xl[(size_t)16384*512];
__device__ __half g_Yh[(size_t)32768*256],  g_Yl[(size_t)32768*256];
__device__ __half g_YTh[(size_t)16*256*2048], g_YTl[(size_t)16*256*2048];
__device__ __half g_Mh[256*512],  g_Ml[256*512];    // (WqWk^T)^T : [256f, 512e]
__device__ __half g_Nh[512*256],  g_Nl[512*256];    // (WvWo)^T   : [512e, 256f]
__device__ __half g_Th[(size_t)16384*256],  g_Tl[(size_t)16384*256];
__device__ float  g_S[(size_t)16*1024*2048];
__device__ __half g_Ph[(size_t)16384*2048];
__device__ __half g_Ch[(size_t)16384*256],  g_Cl[(size_t)16384*256];
__device__ float  g_hv[256];       // Wk @ bq
__device__ float  g_wv[32768];     // Y @ (Wk @ bq)  (per-key logit bias)
__device__ float  g_ob[512];       // bv @ Wo + bo

// ---------------- helpers ---------------------------------------------------
__device__ __forceinline__ uint32_t smem_u32(const void* p) {
    uint32_t a;
    asm("{ .reg .u64 t; cvta.to.shared.u64 t, %1; cvt.u32.u64 %0, t; }"
        : "=r"(a) : "l"(p));
    return a;
}
__device__ __forceinline__ void cp16(uint32_t dst, const void* src) {
    asm volatile("cp.async.cg.shared.global [%0], [%1], 16;"
                 :: "r"(dst), "l"(src) : "memory");
}
__device__ __forceinline__ void cp_commit() {
    asm volatile("cp.async.commit_group;" ::: "memory");
}
__device__ __forceinline__ void cp_wait1() {
    asm volatile("cp.async.wait_group 1;" ::: "memory");
}
__device__ __forceinline__ void ldm4(uint32_t* r, uint32_t addr) {
    asm volatile("ldmatrix.sync.aligned.m8n8.x4.shared.b16 {%0,%1,%2,%3}, [%4];"
                 : "=r"(r[0]), "=r"(r[1]), "=r"(r[2]), "=r"(r[3]) : "r"(addr));
}
__device__ __forceinline__ void mma16816(float* d, const uint32_t* a,
                                         uint32_t b0, uint32_t b1) {
    asm volatile(
        "mma.sync.aligned.m16n8k16.row.col.f32.f16.f16.f32 "
        "{%0,%1,%2,%3}, {%4,%5,%6,%7}, {%8,%9}, {%0,%1,%2,%3};"
        : "+f"(d[0]), "+f"(d[1]), "+f"(d[2]), "+f"(d[3])
        : "r"(a[0]), "r"(a[1]), "r"(a[2]), "r"(a[3]), "r"(b0), "r"(b1));
}
__device__ __forceinline__ uint32_t pk2h(__half a, __half b) {
    return ((uint32_t)__half_as_ushort(b) << 16) | (uint32_t)__half_as_ushort(a);
}
__device__ __forceinline__ void split_h(float x, __half& hi, __half& lo) {
    hi = __float2half(x);
    lo = __float2half(x - __half2float(hi));
}
__device__ __forceinline__ void grid_dep_sync() {
#if __CUDA_ARCH__ >= 900
    cudaGridDependencySynchronize();
#endif
}

// ---------------------------------------------------------------------------
// Split-fp16 GEMM. A:[Mtot,K], B:[Ntot,K] row-major hi/lo.
// TERMS=3: AhBh+AlBh+AhBl.  TERMS=2: AhBh+AlBh.  TERMS=1: AhBh only.
// Tile 128x256, BK=32, 3-stage cp.async, 16 warps (4Mx4N).
// EPI: 0 = fp32 out, 1 = split-fp16 out. BIAS: 0 none, 1 per-n (z-strided).
// ---------------------------------------------------------------------------
struct GemmArgs {
    const __half *Ah, *Al, *Bh, *Bl;
    const float* bias;
    float* outF;
    __half *outH, *outL;
    int K;
    long long aZ, bZ, outZ;
    int ldc;
    int biasZ;
};

template <int TERMS, int EPI, int BIAS>
__global__ __launch_bounds__(512, 1)
void gemm_mma(GemmArgs g)
{
    constexpr int NA = (TERMS >= 2) ? 2 : 1;               // A tiles (Ah[,Al])
    constexpr int OFF_AH = 0;
    constexpr int OFF_AL = A_TILE_B;                       // valid iff NA==2
    constexpr int OFF_BH = NA * A_TILE_B;
    constexpr int OFF_BL = NA * A_TILE_B + B_TILE_B;       // TERMS==3 only
    constexpr int STAGE_B = NA * A_TILE_B + (TERMS == 3 ? 2 : 1) * B_TILE_B;

    extern __shared__ char smem[];
    const uint32_t sm0 = smem_u32(smem);
    const int tid = threadIdx.x, lane = tid & 31, wid = tid >> 5;
    const int wm = wid & 3, wn = wid >> 2;
    const int z = blockIdx.z;
    const int m0 = blockIdx.y * 128, n0 = blockIdx.x * 256;
    const int K = g.K, nkt = K / BK;

    const __half* sAh = g.Ah + (size_t)z * g.aZ + (size_t)m0 * K;
    const __half* sAl = (TERMS >= 2) ? g.Al + (size_t)z * g.aZ + (size_t)m0 * K : nullptr;
    const __half* sBh = g.Bh + (size_t)z * g.bZ + (size_t)n0 * K;
    const __half* sBl = (TERMS == 3) ? g.Bl + (size_t)z * g.bZ + (size_t)n0 * K : nullptr;
    const float* bp = (BIAS == 1) ? (g.bias + (size_t)z * g.biasZ) : nullptr;

    const int lr = tid >> 2, lc = tid & 3;

    float acc[2][8][4];
#pragma unroll
    for (int i = 0; i < 2; i++)
#pragma unroll
        for (int j = 0; j < 8; j++)
#pragma unroll
            for (int e = 0; e < 4; e++) acc[i][j][e] = 0.0f;

    const uint32_t aoff = (uint32_t)(wm * 32 + (lane & 7) + ((lane >> 3) & 1) * 8) * TROW
                        + (lane >> 4) * 16;
    const uint32_t boff = (uint32_t)(wn * 64 + (lane & 7) + ((lane >> 4) & 1) * 8) * TROW
                        + ((lane >> 3) & 1) * 16;

    auto load_stage = [&](int kt, int s) {
        const uint32_t stb = sm0 + s * STAGE_B;
        const size_t kofs = (size_t)kt * BK;
        const uint32_t drow = (uint32_t)lr * TROW + lc * 16;
        const size_t srow = (size_t)lr * K + kofs + lc * 8;
        cp16(stb + OFF_AH + drow, sAh + srow);
        if (TERMS >= 2) cp16(stb + OFF_AL + drow, sAl + srow);
#pragma unroll
        for (int h = 0; h < 2; h++) {
            const uint32_t r = lr + h * 128;
            const uint32_t d2 = (uint32_t)r * TROW + lc * 16;
            const size_t s2 = (size_t)r * K + kofs + lc * 8;
            cp16(stb + OFF_BH + d2, sBh + s2);
            if (TERMS == 3) cp16(stb + OFF_BL + d2, sBl + s2);
        }
    };

    auto compute_stage = [&](int s) {
        const uint32_t stb = sm0 + s * STAGE_B;
#pragma unroll
        for (int ks = 0; ks < 2; ks++) {
            uint32_t aH[2][4], aL[2][4], bB[4][4];
#pragma unroll
            for (int mt = 0; mt < 2; mt++) {
                const uint32_t o = aoff + (uint32_t)mt * 16 * TROW + ks * 32;
                ldm4(aH[mt], stb + OFF_AH + o);
                if (TERMS >= 2) ldm4(aL[mt], stb + OFF_AL + o);
            }
#pragma unroll
            for (int np = 0; np < 4; np++)
                ldm4(bB[np], stb + OFF_BH + boff + (uint32_t)np * 16 * TROW + ks * 32);
            // Ah @ Bh
#pragma unroll
            for (int mt = 0; mt < 2; mt++)
#pragma unroll
                for (int nt = 0; nt < 8; nt++) {
                    const uint32_t* b = &bB[nt >> 1][(nt & 1) * 2];
                    mma16816(acc[mt][nt], aH[mt], b[0], b[1]);
                }
            // Al @ Bh
            if (TERMS >= 2) {
#pragma unroll
                for (int mt = 0; mt < 2; mt++)
#pragma unroll
                    for (int nt = 0; nt < 8; nt++) {
                        const uint32_t* b = &bB[nt >> 1][(nt & 1) * 2];
                        mma16816(acc[mt][nt], aL[mt], b[0], b[1]);
                    }
            }
            if (TERMS == 3) {
#pragma unroll
                for (int np = 0; np < 4; np++)
                    ldm4(bB[np], stb + OFF_BL + boff + (uint32_t)np * 16 * TROW + ks * 32);
#pragma unroll
                for (int mt = 0; mt < 2; mt++)
#pragma unroll
                    for (int nt = 0; nt < 8; nt++) {
                        const uint32_t* b = &bB[nt >> 1][(nt & 1) * 2];
                        mma16816(acc[mt][nt], aH[mt], b[0], b[1]);
                    }
            }
        }
    };

    grid_dep_sync();

#pragma unroll
    for (int s = 0; s < STAGES - 1; s++) { load_stage(s, s); cp_commit(); }
    for (int kt = 0; kt < nkt; kt++) {
        cp_wait1();
        __syncthreads();
        const int nx = kt + STAGES - 1;
        if (nx < nkt) load_stage(nx, nx % STAGES);
        cp_commit();
        compute_stage(kt % STAGES);
    }

    // ---------------- epilogue --------------------------------------------
    const int rr = lane >> 2, rc = (lane & 3) * 2;
#pragma unroll
    for (int mt = 0; mt < 2; mt++) {
#pragma unroll
        for (int nt = 0; nt < 8; nt++) {
            float* d = acc[mt][nt];
            const int m = m0 + wm * 32 + mt * 16 + rr;
            const int n = n0 + wn * 64 + nt * 8 + rc;
            float v[4] = {d[0], d[1], d[2], d[3]};
            if (BIAS == 1) {
                const float b0v = bp[n], b1v = bp[n + 1];
                v[0] += b0v; v[1] += b1v; v[2] += b0v; v[3] += b1v;
            }
            if (EPI == 0) {
                float* o = g.outF + (size_t)z * g.outZ;
                *(float2*)&o[(size_t)m * g.ldc + n]       = make_float2(v[0], v[1]);
                *(float2*)&o[(size_t)(m + 8) * g.ldc + n] = make_float2(v[2], v[3]);
            } else {
                __half hi[4], lo[4];
#pragma unroll
                for (int e = 0; e < 4; e++) split_h(v[e], hi[e], lo[e]);
                __half* oh = g.outH + (size_t)z * g.outZ;
                __half* ol = g.outL + (size_t)z * g.outZ;
                *(uint32_t*)&oh[(size_t)m * g.ldc + n]       = pk2h(hi[0], hi[1]);
                *(uint32_t*)&oh[(size_t)(m + 8) * g.ldc + n] = pk2h(hi[2], hi[3]);
                *(uint32_t*)&ol[(size_t)m * g.ldc + n]       = pk2h(lo[0], lo[1]);
                *(uint32_t*)&ol[(size_t)(m + 8) * g.ldc + n] = pk2h(lo[2], lo[3]);
            }
        }
    }
}

// ---------------------------------------------------------------------------
// prep_hv: hv[f] = Wk[f,:] . bq  (single block)
// ---------------------------------------------------------------------------
__global__ __launch_bounds__(256)
void prep_hv(const float* __restrict__ Wk, const float* __restrict__ bq,
             float* __restrict__ hv)
{
    grid_dep_sync();
    const int f = threadIdx.x;
    float s = 0.0f;
    for (int a = 0; a < 512; a++) s = fmaf(Wk[(size_t)f * 512 + a], bq[a], s);
    hv[f] = s;
}

// ---------------------------------------------------------------------------
// Fused prep mega-kernel: blockIdx.x ranges dispatch independent jobs.
// ---------------------------------------------------------------------------
#define FP_SPLITX0   0
#define FP_SPLITY0   4096
#define FP_TRANS0    8192
#define FP_MT0       10240
#define FP_WV0       10304
#define FP_NT0       14400
#define FP_OB0       14464
#define FP_NBLK      14465

struct PrepArgs {
    const float *X, *Y, *Wq, *Wk, *Wv, *Wo, *bv, *bo, *hv;
    __half *Xh, *Xl, *Yh, *Yl, *YTh, *YTl, *Mh, *Ml, *Nh, *Nl;
    float *wv, *ob;
};

__global__ __launch_bounds__(256)
void fused_prep(PrepArgs p)
{
    __shared__ __align__(16) char smbuf[24960];
    const int blk = blockIdx.x;
    const int tid = threadIdx.x;

    grid_dep_sync();

    if (blk < FP_SPLITY0) {
        // ---- splitX
        const size_t id = (size_t)(blk - FP_SPLITX0) * 256 + tid;
        float v[8];
        *(float4*)&v[0] = ((const float4*)p.X)[id * 2];
        *(float4*)&v[4] = ((const float4*)p.X)[id * 2 + 1];
        __half hi[8], lo[8];
#pragma unroll
        for (int e = 0; e < 8; e++) split_h(v[e], hi[e], lo[e]);
        uint4 hv4, lv4;
        hv4.x = pk2h(hi[0],hi[1]); hv4.y = pk2h(hi[2],hi[3]);
        hv4.z = pk2h(hi[4],hi[5]); hv4.w = pk2h(hi[6],hi[7]);
        lv4.x = pk2h(lo[0],lo[1]); lv4.y = pk2h(lo[2],lo[3]);
        lv4.z = pk2h(lo[4],lo[5]); lv4.w = pk2h(lo[6],lo[7]);
        *(uint4*)&p.Xh[id * 8] = hv4;
        *(uint4*)&p.Xl[id * 8] = lv4;
    } else if (blk < FP_TRANS0) {
        // ---- splitY
        const size_t id = (size_t)(blk - FP_SPLITY0) * 256 + tid;
        float v[8];
        *(float4*)&v[0] = ((const float4*)p.Y)[id * 2];
        *(float4*)&v[4] = ((const float4*)p.Y)[id * 2 + 1];
        __half hi[8], lo[8];
#pragma unroll
        for (int e = 0; e < 8; e++) split_h(v[e], hi[e], lo[e]);
        uint4 hv4, lv4;
        hv4.x = pk2h(hi[0],hi[1]); hv4.y = pk2h(hi[2],hi[3]);
        hv4.z = pk2h(hi[4],hi[5]); hv4.w = pk2h(hi[6],hi[7]);
        lv4.x = pk2h(lo[0],lo[1]); lv4.y = pk2h(lo[2],lo[3]);
        lv4.z = pk2h(lo[4],lo[5]); lv4.w = pk2h(lo[6],lo[7]);
        *(uint4*)&p.Yh[id * 8] = hv4;
        *(uint4*)&p.Yl[id * 8] = lv4;
    } else if (blk < FP_MT0) {
        // ---- transpose_split: Y [2048,256] -> Y^T split [256,2048] x16
        float (*t)[65] = (float(*)[65])smbuf;
        const int idx = blk - FP_TRANS0;
        const int z  = idx >> 7;
        const int r7 = idx & 127;
        const int k0 = (r7 >> 2) * 64;
        const int f0 = (r7 & 3) * 64;
        const float* Yb = p.Y + (size_t)z * 2048 * 256;

        for (int i = tid; i < 64 * 16; i += 256) {
            const int r = i >> 4, c4 = i & 15;
            const float4 v = *(const float4*)&Yb[(size_t)(k0 + r) * 256 + f0 + c4 * 4];
            t[r][c4 * 4 + 0] = v.x; t[r][c4 * 4 + 1] = v.y;
            t[r][c4 * 4 + 2] = v.z; t[r][c4 * 4 + 3] = v.w;
        }
        __syncthreads();
        __half* thb = p.YTh + (size_t)z * 256 * 2048;
        __half* tlb = p.YTl + (size_t)z * 256 * 2048;
        for (int i = tid; i < 64 * 16; i += 256) {
            const int f = i >> 4, c4 = i & 15;
            __half hi[4], lo[4];
#pragma unroll
            for (int e = 0; e < 4; e++) split_h(t[c4 * 4 + e][f], hi[e], lo[e]);
            uint2 hv2, lv2;
            hv2.x = pk2h(hi[0], hi[1]); hv2.y = pk2h(hi[2], hi[3]);
            lv2.x = pk2h(lo[0], lo[1]); lv2.y = pk2h(lo[2], lo[3]);
            *(uint2*)&thb[(size_t)(f0 + f) * 2048 + k0 + c4 * 4] = hv2;
            *(uint2*)&tlb[(size_t)(f0 + f) * 2048 + k0 + c4 * 4] = lv2;
        }
    } else if (blk < FP_WV0) {
        // ---- prep_MT: MT[f,e] = Wk[f,:]·Wq[e,:]  (32f x 64e tile)
        float (*As)[65] = (float(*)[65])smbuf;
        float (*Bs)[65] = (float(*)[65])(smbuf + 32*65*4);
        const int idx = blk - FP_MT0;
        const int e0 = (idx & 7) * 64, f0 = (idx >> 3) * 32;
        const int tx = tid & 15, ty = tid >> 4;

        float acc[2][4] = {};
        for (int a0 = 0; a0 < 512; a0 += 64) {
#pragma unroll
            for (int it = 0; it < 2; it++) {
                const int j = tid + it * 256;
                const int r = j >> 4, c4 = j & 15;
                const float4 v = *(const float4*)&p.Wk[(size_t)(f0 + r) * 512 + a0 + c4 * 4];
                As[r][c4*4+0] = v.x; As[r][c4*4+1] = v.y;
                As[r][c4*4+2] = v.z; As[r][c4*4+3] = v.w;
            }
#pragma unroll
            for (int it = 0; it < 4; it++) {
                const int j = tid + it * 256;
                const int r = j >> 4, c4 = j & 15;
                const float4 v = *(const float4*)&p.Wq[(size_t)(e0 + r) * 512 + a0 + c4 * 4];
                Bs[r][c4*4+0] = v.x; Bs[r][c4*4+1] = v.y;
                Bs[r][c4*4+2] = v.z; Bs[r][c4*4+3] = v.w;
            }
            __syncthreads();
#pragma unroll 8
            for (int a = 0; a < 64; a++) {
                const float a0v = As[ty*2][a], a1v = As[ty*2+1][a];
                float b[4];
#pragma unroll
                for (int j = 0; j < 4; j++) b[j] = Bs[tx*4+j][a];
#pragma unroll
                for (int j = 0; j < 4; j++) {
                    acc[0][j] = fmaf(a0v, b[j], acc[0][j]);
                    acc[1][j] = fmaf(a1v, b[j], acc[1][j]);
                }
            }
            __syncthreads();
        }
#pragma unroll
        for (int i = 0; i < 2; i++) {
            const int f = f0 + ty*2 + i;
            __half hi[4], lo[4];
#pragma unroll
            for (int j = 0; j < 4; j++) split_h(acc[i][j], hi[j], lo[j]);
            uint2 hv2, lv2;
            hv2.x = pk2h(hi[0], hi[1]); hv2.y = pk2h(hi[2], hi[3]);
            lv2.x = pk2h(lo[0], lo[1]); lv2.y = pk2h(lo[2], lo[3]);
            *(uint2*)&p.Mh[(size_t)f * 512 + e0 + tx*4] = hv2;
            *(uint2*)&p.Ml[(size_t)f * 512 + e0 + tx*4] = lv2;
        }
    } else if (blk < FP_NT0) {
        // ---- prep_wv: wv[r] = Y[r,:]·hv  (8 rows per block; hv precomputed)
        float* hs = (float*)smbuf;
        if (tid < 256) hs[tid] = p.hv[tid];
        __syncthreads();
        const int lane = tid & 31;
        const int w = tid >> 5;
        const size_t r = (size_t)(blk - FP_WV0) * 8 + w;
        const float* row = p.Y + r * 256;
        float s = 0.0f;
#pragma unroll
        for (int j = 0; j < 8; j++) s = fmaf(row[lane * 8 + j], hs[lane * 8 + j], s);
#pragma unroll
        for (int o = 16; o; o >>= 1) s += __shfl_xor_sync(0xffffffffu, s, o);
        if (lane == 0) p.wv[r] = s;
    } else if (blk < FP_OB0) {
        // ---- prep_NT: NT[e,f] = Wv[f,:]·Wo[:,e]  (64e x 32f tile)
        float (*Os)[65] = (float(*)[65])smbuf;
        float (*Vs)[65] = (float(*)[65])(smbuf + 64*65*4);
        const int idx = blk - FP_NT0;
        const int f0 = (idx & 7) * 32, e0 = (idx >> 3) * 64;
        const int tx = tid & 15, ty = tid >> 4;

        float acc[4][2] = {};
        for (int a0 = 0; a0 < 512; a0 += 64) {
#pragma unroll
            for (int it = 0; it < 4; it++) {
                const int j = tid + it * 256;
                const int r = j >> 4, c4 = j & 15;
                const float4 v = *(const float4*)&p.Wo[(size_t)(a0 + r) * 512 + e0 + c4 * 4];
                Os[r][c4*4+0] = v.x; Os[r][c4*4+1] = v.y;
                Os[r][c4*4+2] = v.z; Os[r][c4*4+3] = v.w;
            }
#pragma unroll
            for (int it = 0; it < 2; it++) {
                const int j = tid + it * 256;
                const int r = j >> 4, c4 = j & 15;
                const float4 v = *(const float4*)&p.Wv[(size_t)(f0 + r) * 512 + a0 + c4 * 4];
                Vs[r][c4*4+0] = v.x; Vs[r][c4*4+1] = v.y;
                Vs[r][c4*4+2] = v.z; Vs[r][c4*4+3] = v.w;
            }
            __syncthreads();
#pragma unroll 8
            for (int a = 0; a < 64; a++) {
                float e4[4], fv0, fv1;
#pragma unroll
                for (int i = 0; i < 4; i++) e4[i] = Os[a][ty*4+i];
                fv0 = Vs[tx*2][a]; fv1 = Vs[tx*2+1][a];
#pragma unroll
                for (int i = 0; i < 4; i++) {
                    acc[i][0] = fmaf(e4[i], fv0, acc[i][0]);
                    acc[i][1] = fmaf(e4[i], fv1, acc[i][1]);
                }
            }
            __syncthreads();
        }
#pragma unroll
        for (int i = 0; i < 4; i++) {
            const int e = e0 + ty*4 + i;
            __half hi[2], lo[2];
#pragma unroll
            for (int j = 0; j < 2; j++) split_h(acc[i][j], hi[j], lo[j]);
            *(uint32_t*)&p.Nh[(size_t)e * 256 + f0 + tx*2] = pk2h(hi[0], hi[1]);
            *(uint32_t*)&p.Nl[(size_t)e * 256 + f0 + tx*2] = pk2h(lo[0], lo[1]);
        }
    } else {
        // ---- prep_ob: ob[e] = bo[e] + bv·Wo[:,e]
#pragma unroll
        for (int half = 0; half < 2; half++) {
            const int e = tid + half * 256;
            float s = p.bo[e];
            for (int a = 0; a < 512; a++)
                s = fmaf(p.bv[a], p.Wo[(size_t)a * 512 + e], s);
            p.ob[e] = s;
        }
    }
}

// ---------------------------------------------------------------------------
// Softmax over 2048-col fp32 rows -> fp16 (hi only)
// ---------------------------------------------------------------------------
__global__ __launch_bounds__(256)
void softmax_h(const float* __restrict__ S, __half* __restrict__ Sh)
{
    const size_t r = blockIdx.x;
    const float* row = S + r * 2048;
    const int tid = threadIdx.x;
    const int c0 = tid * 8;

    grid_dep_sync();

    float v[8];
    *(float4*)&v[0] = *(const float4*)&row[c0];
    *(float4*)&v[4] = *(const float4*)&row[c0 + 4];

    __shared__ float red[8];
    float m = v[0];
#pragma unroll
    for (int e = 1; e < 8; e++) m = fmaxf(m, v[e]);
#pragma unroll
    for (int o = 16; o; o >>= 1) m = fmaxf(m, __shfl_xor_sync(0xffffffffu, m, o));
    if ((tid & 31) == 0) red[tid >> 5] = m;
    __syncthreads();
    float mx = red[0];
#pragma unroll
    for (int i = 1; i < 8; i++) mx = fmaxf(mx, red[i]);
    __syncthreads();

    float s = 0.0f;
#pragma unroll
    for (int e = 0; e < 8; e++) { v[e] = __expf(v[e] - mx); s += v[e]; }
#pragma unroll
    for (int o = 16; o; o >>= 1) s += __shfl_xor_sync(0xffffffffu, s, o);
    if ((tid & 31) == 0) red[tid >> 5] = s;
    __syncthreads();
    float st = 0.0f;
#pragma unroll
    for (int i = 0; i < 8; i++) st += red[i];
    const float inv = 1.0f / st;

    __half hi[8];
#pragma unroll
    for (int e = 0; e < 8; e++) hi[e] = __float2half(v[e] * inv);
    uint4 hv4;
    hv4.x = pk2h(hi[0],hi[1]); hv4.y = pk2h(hi[2],hi[3]);
    hv4.z = pk2h(hi[4],hi[5]); hv4.w = pk2h(hi[6],hi[7]);
    *(uint4*)&Sh[r * 2048 + c0] = hv4;
}

// ---------------------------------------------------------------------------
// Launch — all kernels via PDL (programmatic stream serialization)
// ---------------------------------------------------------------------------
template <typename F, typename... Args>
static inline void launch_pdl(dim3 grid, dim3 block, size_t smem,
                              F func, Args... args)
{
    cudaLaunchConfig_t cfg = {};
    cfg.gridDim = grid;
    cfg.blockDim = block;
    cfg.dynamicSmemBytes = smem;
    cfg.stream = 0;
    cudaLaunchAttribute at[1];
    at[0].id = cudaLaunchAttributeProgrammaticStreamSerialization;
    at[0].val.programmaticStreamSerializationAllowed = 1;
    cfg.attrs = at;
    cfg.numAttrs = 1;
    cudaLaunchKernelEx(&cfg, func, args...);
}

extern "C" void kernel_launch(void* const* d_in, const int* in_sizes, int n_in,
                              void* d_out, int out_size)
{
    const float* X  = (const float*)d_in[0];
    const float* Y  = (const float*)d_in[1];
    const float* Wq = (const float*)d_in[2];
    const float* bq = (const float*)d_in[3];
    const float* Wk = (const float*)d_in[4];
    const float* Wv = (const float*)d_in[6];
    const float* bv = (const float*)d_in[7];
    const float* Wo = (const float*)d_in[8];
    const float* bo = (const float*)d_in[9];
    float* out = (float*)d_out;

    constexpr int SMEM3 = STAGES * (2 * A_TILE_B + 2 * B_TILE_B);   // 184320
    constexpr int SMEM2 = STAGES * (2 * A_TILE_B + 1 * B_TILE_B);   // 122880
    constexpr int SMEM1 = STAGES * (1 * A_TILE_B + 1 * B_TILE_B);   // 92160
    cudaFuncSetAttribute(gemm_mma<3,0,1>, cudaFuncAttributeMaxDynamicSharedMemorySize, SMEM3);
    cudaFuncSetAttribute(gemm_mma<3,1,0>, cudaFuncAttributeMaxDynamicSharedMemorySize, SMEM3);
    cudaFuncSetAttribute(gemm_mma<1,1,0>, cudaFuncAttributeMaxDynamicSharedMemorySize, SMEM1);
    cudaFuncSetAttribute(gemm_mma<2,0,1>, cudaFuncAttributeMaxDynamicSharedMemorySize, SMEM2);

    __half *Xh,*Xl,*Yh,*Yl,*YTh,*YTl,*Mh,*Ml,*Nh,*Nl,*Th,*Tl,*Ph,*Ch,*Cl;
    float *S,*hv,*wv,*ob;
    cudaGetSymbolAddress((void**)&Xh, g_Xh);   cudaGetSymbolAddress((void**)&Xl, g_Xl);
    cudaGetSymbolAddress((void**)&Yh, g_Yh);   cudaGetSymbolAddress((void**)&Yl, g_Yl);
    cudaGetSymbolAddress((void**)&YTh, g_YTh); cudaGetSymbolAddress((void**)&YTl, g_YTl);
    cudaGetSymbolAddress((void**)&Mh, g_Mh);   cudaGetSymbolAddress((void**)&Ml, g_Ml);
    cudaGetSymbolAddress((void**)&Nh, g_Nh);   cudaGetSymbolAddress((void**)&Nl, g_Nl);
    cudaGetSymbolAddress((void**)&Th, g_Th);   cudaGetSymbolAddress((void**)&Tl, g_Tl);
    cudaGetSymbolAddress((void**)&Ph, g_Ph);
    cudaGetSymbolAddress((void**)&Ch, g_Ch);   cudaGetSymbolAddress((void**)&Cl, g_Cl);
    cudaGetSymbolAddress((void**)&S, g_S);
    cudaGetSymbolAddress((void**)&hv, g_hv);
    cudaGetSymbolAddress((void**)&wv, g_wv);
    cudaGetSymbolAddress((void**)&ob, g_ob);

    // 1: hv (feeds wv inside fused prep)
    launch_pdl(dim3(1), dim3(256), 0, prep_hv, Wk, bq, hv);
    // 2: fused prep
    {
        PrepArgs p{X, Y, Wq, Wk, Wv, Wo, bv, bo, hv,
                   Xh, Xl, Yh, Yl, YTh, YTl, Mh, Ml, Nh, Nl,
                   wv, ob};
        launch_pdl(dim3(FP_NBLK), dim3(256), 0, fused_prep, p);
    }
    // 3: T = X @ M -> split [16384,256]   (3-term)
    {
        GemmArgs a{Xh, Xl, Mh, Ml, nullptr, nullptr, Th, Tl,
                   512, 0, 0, 0, 256, 0};
        launch_pdl(dim3(1,128,1), dim3(512), SMEM3, gemm_mma<3,1,0>, a);
    }
    // 4: S = T_z @ Y_z^T + wv -> fp32 [1024,2048] x16   (3-term)
    {
        GemmArgs a{Th, Tl, Yh, Yl, wv, S, nullptr, nullptr,
                   256, (long long)1024*256, (long long)2048*256,
                   (long long)1024*2048, 2048, 2048};
        launch_pdl(dim3(8,8,16), dim3(512), SMEM3, gemm_mma<3,0,1>, a);
    }
    // 5: softmax -> Ph (hi only)
    launch_pdl(dim3(16384), dim3(256), 0, softmax_h, S, Ph);
    // 6: C = Ph @ Yh -> split [1024,256] x16   (1-term)
    {
        GemmArgs a{Ph, nullptr, YTh, nullptr, nullptr, nullptr, Ch, Cl,
                   2048, (long long)1024*2048, (long long)256*2048,
                   (long long)1024*256, 256, 0};
        launch_pdl(dim3(1,8,16), dim3(512), SMEM1, gemm_mma<1,1,0>, a);
    }
    // 7: out = (Ch+Cl) @ Nh + ob -> fp32 [16384,512]   (2-term)
    {
        GemmArgs a{Ch, Cl, Nh, nullptr, ob, out, nullptr, nullptr,
                   256, 0, 0, 0, 512, 0};
        launch_pdl(dim3(2,128,1), dim3(512), SMEM2, gemm_mma<2,0,1>, a);
    }
}

// round 17
// speedup vs baseline: 1.9900x; 1.0074x over previous
#include <cuda_runtime.h>
#include <cuda_fp16.h>
#include <cstdint>
#include <cstddef>

// ---------------------------------------------------------------------------
// CrossAttention on sm_100 via mma.sync fp16 (HMMA), split fp32 accum.
// R17: fused_prep slimmed — YTl dead-store removed (C is 1-term), prep_wv
// folded into splitY (same geometry; bit-identical math). PDL kept.
//   S = X(WqWk^T)Y^T + wv ;  out = (P@Y)@(WvWo) + (bv·Wo+bo)
// ---------------------------------------------------------------------------

#define STAGES 3
#define BK 32
#define TROW 80                     // padded smem row bytes (40 fp16)
#define A_TILE_B (128 * TROW)       // 10240
#define B_TILE_B (256 * TROW)       // 20480

// ---------------- scratch (device globals) ---------------------------------
__device__ __half g_Xh[(size_t)16384*512],  g_Xl[(size_t)16384*512];
__device__ __half g_Yh[(size_t)32768*256],  g_Yl[(size_t)32768*256];
__device__ __half g_YTh[(size_t)16*256*2048];
__device__ __half g_Mh[256*512],  g_Ml[256*512];    // (WqWk^T)^T : [256f, 512e]
__device__ __half g_Nh[512*256],  g_Nl[512*256];    // (WvWo)^T   : [512e, 256f]
__device__ __half g_Th[(size_t)16384*256],  g_Tl[(size_t)16384*256];
__device__ float  g_S[(size_t)16*1024*2048];
__device__ __half g_Ph[(size_t)16384*2048];
__device__ __half g_Ch[(size_t)16384*256],  g_Cl[(size_t)16384*256];
__device__ float  g_hv[256];       // Wk @ bq
__device__ float  g_wv[32768];     // Y @ (Wk @ bq)  (per-key logit bias)
__device__ float  g_ob[512];       // bv @ Wo + bo

// ---------------- helpers ---------------------------------------------------
__device__ __forceinline__ uint32_t smem_u32(const void* p) {
    uint32_t a;
    asm("{ .reg .u64 t; cvta.to.shared.u64 t, %1; cvt.u32.u64 %0, t; }"
        : "=r"(a) : "l"(p));
    return a;
}
__device__ __forceinline__ void cp16(uint32_t dst, const void* src) {
    asm volatile("cp.async.cg.shared.global [%0], [%1], 16;"
                 :: "r"(dst), "l"(src) : "memory");
}
__device__ __forceinline__ void cp_commit() {
    asm volatile("cp.async.commit_group;" ::: "memory");
}
__device__ __forceinline__ void cp_wait1() {
    asm volatile("cp.async.wait_group 1;" ::: "memory");
}
__device__ __forceinline__ void ldm4(uint32_t* r, uint32_t addr) {
    asm volatile("ldmatrix.sync.aligned.m8n8.x4.shared.b16 {%0,%1,%2,%3}, [%4];"
                 : "=r"(r[0]), "=r"(r[1]), "=r"(r[2]), "=r"(r[3]) : "r"(addr));
}
__device__ __forceinline__ void mma16816(float* d, const uint32_t* a,
                                         uint32_t b0, uint32_t b1) {
    asm volatile(
        "mma.sync.aligned.m16n8k16.row.col.f32.f16.f16.f32 "
        "{%0,%1,%2,%3}, {%4,%5,%6,%7}, {%8,%9}, {%0,%1,%2,%3};"
        : "+f"(d[0]), "+f"(d[1]), "+f"(d[2]), "+f"(d[3])
        : "r"(a[0]), "r"(a[1]), "r"(a[2]), "r"(a[3]), "r"(b0), "r"(b1));
}
__device__ __forceinline__ uint32_t pk2h(__half a, __half b) {
    return ((uint32_t)__half_as_ushort(b) << 16) | (uint32_t)__half_as_ushort(a);
}
__device__ __forceinline__ void split_h(float x, __half& hi, __half& lo) {
    hi = __float2half(x);
    lo = __float2half(x - __half2float(hi));
}
__device__ __forceinline__ void grid_dep_sync() {
#if __CUDA_ARCH__ >= 900
    cudaGridDependencySynchronize();
#endif
}

// ---------------------------------------------------------------------------
// Split-fp16 GEMM. A:[Mtot,K], B:[Ntot,K] row-major hi/lo.
// TERMS=3: AhBh+AlBh+AhBl.  TERMS=2: AhBh+AlBh.  TERMS=1: AhBh only.
// Tile 128x256, BK=32, 3-stage cp.async, 16 warps (4Mx4N).
// EPI: 0 = fp32 out, 1 = split-fp16 out. BIAS: 0 none, 1 per-n (z-strided).
// ---------------------------------------------------------------------------
struct GemmArgs {
    const __half *Ah, *Al, *Bh, *Bl;
    const float* bias;
    float* outF;
    __half *outH, *outL;
    int K;
    long long aZ, bZ, outZ;
    int ldc;
    int biasZ;
};

template <int TERMS, int EPI, int BIAS>
__global__ __launch_bounds__(512, 1)
void gemm_mma(GemmArgs g)
{
    constexpr int NA = (TERMS >= 2) ? 2 : 1;               // A tiles (Ah[,Al])
    constexpr int OFF_AH = 0;
    constexpr int OFF_AL = A_TILE_B;                       // valid iff NA==2
    constexpr int OFF_BH = NA * A_TILE_B;
    constexpr int OFF_BL = NA * A_TILE_B + B_TILE_B;       // TERMS==3 only
    constexpr int STAGE_B = NA * A_TILE_B + (TERMS == 3 ? 2 : 1) * B_TILE_B;

    extern __shared__ char smem[];
    const uint32_t sm0 = smem_u32(smem);
    const int tid = threadIdx.x, lane = tid & 31, wid = tid >> 5;
    const int wm = wid & 3, wn = wid >> 2;
    const int z = blockIdx.z;
    const int m0 = blockIdx.y * 128, n0 = blockIdx.x * 256;
    const int K = g.K, nkt = K / BK;

    const __half* sAh = g.Ah + (size_t)z * g.aZ + (size_t)m0 * K;
    const __half* sAl = (TERMS >= 2) ? g.Al + (size_t)z * g.aZ + (size_t)m0 * K : nullptr;
    const __half* sBh = g.Bh + (size_t)z * g.bZ + (size_t)n0 * K;
    const __half* sBl = (TERMS == 3) ? g.Bl + (size_t)z * g.bZ + (size_t)n0 * K : nullptr;
    const float* bp = (BIAS == 1) ? (g.bias + (size_t)z * g.biasZ) : nullptr;

    const int lr = tid >> 2, lc = tid & 3;

    float acc[2][8][4];
#pragma unroll
    for (int i = 0; i < 2; i++)
#pragma unroll
        for (int j = 0; j < 8; j++)
#pragma unroll
            for (int e = 0; e < 4; e++) acc[i][j][e] = 0.0f;

    const uint32_t aoff = (uint32_t)(wm * 32 + (lane & 7) + ((lane >> 3) & 1) * 8) * TROW
                        + (lane >> 4) * 16;
    const uint32_t boff = (uint32_t)(wn * 64 + (lane & 7) + ((lane >> 4) & 1) * 8) * TROW
                        + ((lane >> 3) & 1) * 16;

    auto load_stage = [&](int kt, int s) {
        const uint32_t stb = sm0 + s * STAGE_B;
        const size_t kofs = (size_t)kt * BK;
        const uint32_t drow = (uint32_t)lr * TROW + lc * 16;
        const size_t srow = (size_t)lr * K + kofs + lc * 8;
        cp16(stb + OFF_AH + drow, sAh + srow);
        if (TERMS >= 2) cp16(stb + OFF_AL + drow, sAl + srow);
#pragma unroll
        for (int h = 0; h < 2; h++) {
            const uint32_t r = lr + h * 128;
            const uint32_t d2 = (uint32_t)r * TROW + lc * 16;
            const size_t s2 = (size_t)r * K + kofs + lc * 8;
            cp16(stb + OFF_BH + d2, sBh + s2);
            if (TERMS == 3) cp16(stb + OFF_BL + d2, sBl + s2);
        }
    };

    auto compute_stage = [&](int s) {
        const uint32_t stb = sm0 + s * STAGE_B;
#pragma unroll
        for (int ks = 0; ks < 2; ks++) {
            uint32_t aH[2][4], aL[2][4], bB[4][4];
#pragma unroll
            for (int mt = 0; mt < 2; mt++) {
                const uint32_t o = aoff + (uint32_t)mt * 16 * TROW + ks * 32;
                ldm4(aH[mt], stb + OFF_AH + o);
                if (TERMS >= 2) ldm4(aL[mt], stb + OFF_AL + o);
            }
#pragma unroll
            for (int np = 0; np < 4; np++)
                ldm4(bB[np], stb + OFF_BH + boff + (uint32_t)np * 16 * TROW + ks * 32);
            // Ah @ Bh
#pragma unroll
            for (int mt = 0; mt < 2; mt++)
#pragma unroll
                for (int nt = 0; nt < 8; nt++) {
                    const uint32_t* b = &bB[nt >> 1][(nt & 1) * 2];
                    mma16816(acc[mt][nt], aH[mt], b[0], b[1]);
                }
            // Al @ Bh
            if (TERMS >= 2) {
#pragma unroll
                for (int mt = 0; mt < 2; mt++)
#pragma unroll
                    for (int nt = 0; nt < 8; nt++) {
                        const uint32_t* b = &bB[nt >> 1][(nt & 1) * 2];
                        mma16816(acc[mt][nt], aL[mt], b[0], b[1]);
                    }
            }
            if (TERMS == 3) {
#pragma unroll
                for (int np = 0; np < 4; np++)
                    ldm4(bB[np], stb + OFF_BL + boff + (uint32_t)np * 16 * TROW + ks * 32);
#pragma unroll
                for (int mt = 0; mt < 2; mt++)
#pragma unroll
                    for (int nt = 0; nt < 8; nt++) {
                        const uint32_t* b = &bB[nt >> 1][(nt & 1) * 2];
                        mma16816(acc[mt][nt], aH[mt], b[0], b[1]);
                    }
            }
        }
    };

    grid_dep_sync();

#pragma unroll
    for (int s = 0; s < STAGES - 1; s++) { load_stage(s, s); cp_commit(); }
    for (int kt = 0; kt < nkt; kt++) {
        cp_wait1();
        __syncthreads();
        const int nx = kt + STAGES - 1;
        if (nx < nkt) load_stage(nx, nx % STAGES);
        cp_commit();
        compute_stage(kt % STAGES);
    }

    // ---------------- epilogue --------------------------------------------
    const int rr = lane >> 2, rc = (lane & 3) * 2;
#pragma unroll
    for (int mt = 0; mt < 2; mt++) {
#pragma unroll
        for (int nt = 0; nt < 8; nt++) {
            float* d = acc[mt][nt];
            const int m = m0 + wm * 32 + mt * 16 + rr;
            const int n = n0 + wn * 64 + nt * 8 + rc;
            float v[4] = {d[0], d[1], d[2], d[3]};
            if (BIAS == 1) {
                const float b0v = bp[n], b1v = bp[n + 1];
                v[0] += b0v; v[1] += b1v; v[2] += b0v; v[3] += b1v;
            }
            if (EPI == 0) {
                float* o = g.outF + (size_t)z * g.outZ;
                *(float2*)&o[(size_t)m * g.ldc + n]       = make_float2(v[0], v[1]);
                *(float2*)&o[(size_t)(m + 8) * g.ldc + n] = make_float2(v[2], v[3]);
            } else {
                __half hi[4], lo[4];
#pragma unroll
                for (int e = 0; e < 4; e++) split_h(v[e], hi[e], lo[e]);
                __half* oh = g.outH + (size_t)z * g.outZ;
                __half* ol = g.outL + (size_t)z * g.outZ;
                *(uint32_t*)&oh[(size_t)m * g.ldc + n]       = pk2h(hi[0], hi[1]);
                *(uint32_t*)&oh[(size_t)(m + 8) * g.ldc + n] = pk2h(hi[2], hi[3]);
                *(uint32_t*)&ol[(size_t)m * g.ldc + n]       = pk2h(lo[0], lo[1]);
                *(uint32_t*)&ol[(size_t)(m + 8) * g.ldc + n] = pk2h(lo[2], lo[3]);
            }
        }
    }
}

// ---------------------------------------------------------------------------
// prep_hv: hv[f] = Wk[f,:] . bq  (single block)
// ---------------------------------------------------------------------------
__global__ __launch_bounds__(256)
void prep_hv(const float* __restrict__ Wk, const float* __restrict__ bq,
             float* __restrict__ hv)
{
    grid_dep_sync();
    const int f = threadIdx.x;
    float s = 0.0f;
    for (int a = 0; a < 512; a++) s = fmaf(Wk[(size_t)f * 512 + a], bq[a], s);
    hv[f] = s;
}

// ---------------------------------------------------------------------------
// Fused prep mega-kernel: blockIdx.x ranges dispatch independent jobs.
//  [0,4096)        splitX
//  [4096,8192)     splitY + fused wv (same geometry: 8 rows/block)
//  [8192,10240)    transpose (Yh only; YTl is dead since C is 1-term)
//  [10240,10304)   prep_MT (64)
//  [10304,10368)   prep_NT (64)
//  [10368]         prep_ob (1)
// ---------------------------------------------------------------------------
#define FP_SPLITX0   0
#define FP_SPLITY0   4096
#define FP_TRANS0    8192
#define FP_MT0       10240
#define FP_NT0       10304
#define FP_OB0       10368
#define FP_NBLK      10369

struct PrepArgs {
    const float *X, *Y, *Wq, *Wk, *Wv, *Wo, *bv, *bo, *hv;
    __half *Xh, *Xl, *Yh, *Yl, *YTh, *Mh, *Ml, *Nh, *Nl;
    float *wv, *ob;
};

__global__ __launch_bounds__(256)
void fused_prep(PrepArgs p)
{
    __shared__ __align__(16) char smbuf[24960];
    const int blk = blockIdx.x;
    const int tid = threadIdx.x;

    grid_dep_sync();

    if (blk < FP_SPLITY0) {
        // ---- splitX
        const size_t id = (size_t)(blk - FP_SPLITX0) * 256 + tid;
        float v[8];
        *(float4*)&v[0] = ((const float4*)p.X)[id * 2];
        *(float4*)&v[4] = ((const float4*)p.X)[id * 2 + 1];
        __half hi[8], lo[8];
#pragma unroll
        for (int e = 0; e < 8; e++) split_h(v[e], hi[e], lo[e]);
        uint4 hv4, lv4;
        hv4.x = pk2h(hi[0],hi[1]); hv4.y = pk2h(hi[2],hi[3]);
        hv4.z = pk2h(hi[4],hi[5]); hv4.w = pk2h(hi[6],hi[7]);
        lv4.x = pk2h(lo[0],lo[1]); lv4.y = pk2h(lo[2],lo[3]);
        lv4.z = pk2h(lo[4],lo[5]); lv4.w = pk2h(lo[6],lo[7]);
        *(uint4*)&p.Xh[id * 8] = hv4;
        *(uint4*)&p.Xl[id * 8] = lv4;
    } else if (blk < FP_TRANS0) {
        // ---- splitY + fused wv
        // Block covers 8 consecutive Y rows (2048 elems). Thread tid handles
        // row (tid>>5), cols (tid&31)*8..+7 — identical geometry to old
        // prep_wv, so wv math is bit-identical.
        const int blkY = blk - FP_SPLITY0;
        const size_t id = (size_t)blkY * 256 + tid;
        float v[8];
        *(float4*)&v[0] = ((const float4*)p.Y)[id * 2];
        *(float4*)&v[4] = ((const float4*)p.Y)[id * 2 + 1];
        __half hi[8], lo[8];
#pragma unroll
        for (int e = 0; e < 8; e++) split_h(v[e], hi[e], lo[e]);
        uint4 hv4, lv4;
        hv4.x = pk2h(hi[0],hi[1]); hv4.y = pk2h(hi[2],hi[3]);
        hv4.z = pk2h(hi[4],hi[5]); hv4.w = pk2h(hi[6],hi[7]);
        lv4.x = pk2h(lo[0],lo[1]); lv4.y = pk2h(lo[2],lo[3]);
        lv4.z = pk2h(lo[4],lo[5]); lv4.w = pk2h(lo[6],lo[7]);
        *(uint4*)&p.Yh[id * 8] = hv4;
        *(uint4*)&p.Yl[id * 8] = lv4;
        // wv: dot of this thread's 8 Y values with hv slice, warp-reduce
        const int lane = tid & 31;
        const int w = tid >> 5;
        float s = 0.0f;
#pragma unroll
        for (int j = 0; j < 8; j++)
            s = fmaf(v[j], __ldg(&p.hv[lane * 8 + j]), s);
#pragma unroll
        for (int o = 16; o; o >>= 1) s += __shfl_xor_sync(0xffffffffu, s, o);
        if (lane == 0) p.wv[(size_t)blkY * 8 + w] = s;
    } else if (blk < FP_MT0) {
        // ---- transpose: Y [2048,256] -> Y^T fp16 hi [256,2048] x16
        float (*t)[65] = (float(*)[65])smbuf;
        const int idx = blk - FP_TRANS0;
        const int z  = idx >> 7;
        const int r7 = idx & 127;
        const int k0 = (r7 >> 2) * 64;
        const int f0 = (r7 & 3) * 64;
        const float* Yb = p.Y + (size_t)z * 2048 * 256;

        for (int i = tid; i < 64 * 16; i += 256) {
            const int r = i >> 4, c4 = i & 15;
            const float4 v = *(const float4*)&Yb[(size_t)(k0 + r) * 256 + f0 + c4 * 4];
            t[r][c4 * 4 + 0] = v.x; t[r][c4 * 4 + 1] = v.y;
            t[r][c4 * 4 + 2] = v.z; t[r][c4 * 4 + 3] = v.w;
        }
        __syncthreads();
        __half* thb = p.YTh + (size_t)z * 256 * 2048;
        for (int i = tid; i < 64 * 16; i += 256) {
            const int f = i >> 4, c4 = i & 15;
            __half hi[4];
#pragma unroll
            for (int e = 0; e < 4; e++) hi[e] = __float2half(t[c4 * 4 + e][f]);
            uint2 hv2;
            hv2.x = pk2h(hi[0], hi[1]); hv2.y = pk2h(hi[2], hi[3]);
            *(uint2*)&thb[(size_t)(f0 + f) * 2048 + k0 + c4 * 4] = hv2;
        }
    } else if (blk < FP_NT0) {
        // ---- prep_MT: MT[f,e] = Wk[f,:]·Wq[e,:]  (32f x 64e tile)
        float (*As)[65] = (float(*)[65])smbuf;
        float (*Bs)[65] = (float(*)[65])(smbuf + 32*65*4);
        const int idx = blk - FP_MT0;
        const int e0 = (idx & 7) * 64, f0 = (idx >> 3) * 32;
        const int tx = tid & 15, ty = tid >> 4;

        float acc[2][4] = {};
        for (int a0 = 0; a0 < 512; a0 += 64) {
#pragma unroll
            for (int it = 0; it < 2; it++) {
                const int j = tid + it * 256;
                const int r = j >> 4, c4 = j & 15;
                const float4 v = *(const float4*)&p.Wk[(size_t)(f0 + r) * 512 + a0 + c4 * 4];
                As[r][c4*4+0] = v.x; As[r][c4*4+1] = v.y;
                As[r][c4*4+2] = v.z; As[r][c4*4+3] = v.w;
            }
#pragma unroll
            for (int it = 0; it < 4; it++) {
                const int j = tid + it * 256;
                const int r = j >> 4, c4 = j & 15;
                const float4 v = *(const float4*)&p.Wq[(size_t)(e0 + r) * 512 + a0 + c4 * 4];
                Bs[r][c4*4+0] = v.x; Bs[r][c4*4+1] = v.y;
                Bs[r][c4*4+2] = v.z; Bs[r][c4*4+3] = v.w;
            }
            __syncthreads();
#pragma unroll 8
            for (int a = 0; a < 64; a++) {
                const float a0v = As[ty*2][a], a1v = As[ty*2+1][a];
                float b[4];
#pragma unroll
                for (int j = 0; j < 4; j++) b[j] = Bs[tx*4+j][a];
#pragma unroll
                for (int j = 0; j < 4; j++) {
                    acc[0][j] = fmaf(a0v, b[j], acc[0][j]);
                    acc[1][j] = fmaf(a1v, b[j], acc[1][j]);
                }
            }
            __syncthreads();
        }
#pragma unroll
        for (int i = 0; i < 2; i++) {
            const int f = f0 + ty*2 + i;
            __half hi[4], lo[4];
#pragma unroll
            for (int j = 0; j < 4; j++) split_h(acc[i][j], hi[j], lo[j]);
            uint2 hv2, lv2;
            hv2.x = pk2h(hi[0], hi[1]); hv2.y = pk2h(hi[2], hi[3]);
            lv2.x = pk2h(lo[0], lo[1]); lv2.y = pk2h(lo[2], lo[3]);
            *(uint2*)&p.Mh[(size_t)f * 512 + e0 + tx*4] = hv2;
            *(uint2*)&p.Ml[(size_t)f * 512 + e0 + tx*4] = lv2;
        }
    } else if (blk < FP_OB0) {
        // ---- prep_NT: NT[e,f] = Wv[f,:]·Wo[:,e]  (64e x 32f tile)
        float (*Os)[65] = (float(*)[65])smbuf;
        float (*Vs)[65] = (float(*)[65])(smbuf + 64*65*4);
        const int idx = blk - FP_NT0;
        const int f0 = (idx & 7) * 32, e0 = (idx >> 3) * 64;
        const int tx = tid & 15, ty = tid >> 4;

        float acc[4][2] = {};
        for (int a0 = 0; a0 < 512; a0 += 64) {
#pragma unroll
            for (int it = 0; it < 4; it++) {
                const int j = tid + it * 256;
                const int r = j >> 4, c4 = j & 15;
                const float4 v = *(const float4*)&p.Wo[(size_t)(a0 + r) * 512 + e0 + c4 * 4];
                Os[r][c4*4+0] = v.x; Os[r][c4*4+1] = v.y;
                Os[r][c4*4+2] = v.z; Os[r][c4*4+3] = v.w;
            }
#pragma unroll
            for (int it = 0; it < 2; it++) {
                const int j = tid + it * 256;
                const int r = j >> 4, c4 = j & 15;
                const float4 v = *(const float4*)&p.Wv[(size_t)(f0 + r) * 512 + a0 + c4 * 4];
                Vs[r][c4*4+0] = v.x; Vs[r][c4*4+1] = v.y;
                Vs[r][c4*4+2] = v.z; Vs[r][c4*4+3] = v.w;
            }
            __syncthreads();
#pragma unroll 8
            for (int a = 0; a < 64; a++) {
                float e4[4], fv0, fv1;
#pragma unroll
                for (int i = 0; i < 4; i++) e4[i] = Os[a][ty*4+i];
                fv0 = Vs[tx*2][a]; fv1 = Vs[tx*2+1][a];
#pragma unroll
                for (int i = 0; i < 4; i++) {
                    acc[i][0] = fmaf(e4[i], fv0, acc[i][0]);
                    acc[i][1] = fmaf(e4[i], fv1, acc[i][1]);
                }
            }
            __syncthreads();
        }
#pragma unroll
        for (int i = 0; i < 4; i++) {
            const int e = e0 + ty*4 + i;
            __half hi[2], lo[2];
#pragma unroll
            for (int j = 0; j < 2; j++) split_h(acc[i][j], hi[j], lo[j]);
            *(uint32_t*)&p.Nh[(size_t)e * 256 + f0 + tx*2] = pk2h(hi[0], hi[1]);
            *(uint32_t*)&p.Nl[(size_t)e * 256 + f0 + tx*2] = pk2h(lo[0], lo[1]);
        }
    } else {
        // ---- prep_ob: ob[e] = bo[e] + bv·Wo[:,e]
#pragma unroll
        for (int half = 0; half < 2; half++) {
            const int e = tid + half * 256;
            float s = p.bo[e];
            for (int a = 0; a < 512; a++)
                s = fmaf(p.bv[a], p.Wo[(size_t)a * 512 + e], s);
            p.ob[e] = s;
        }
    }
}

// ---------------------------------------------------------------------------
// Softmax over 2048-col fp32 rows -> fp16 (hi only)
// ---------------------------------------------------------------------------
__global__ __launch_bounds__(256)
void softmax_h(const float* __restrict__ S, __half* __restrict__ Sh)
{
    const size_t r = blockIdx.x;
    const float* row = S + r * 2048;
    const int tid = threadIdx.x;
    const int c0 = tid * 8;

    grid_dep_sync();

    float v[8];
    *(float4*)&v[0] = *(const float4*)&row[c0];
    *(float4*)&v[4] = *(const float4*)&row[c0 + 4];

    __shared__ float red[8];
    float m = v[0];
#pragma unroll
    for (int e = 1; e < 8; e++) m = fmaxf(m, v[e]);
#pragma unroll
    for (int o = 16; o; o >>= 1) m = fmaxf(m, __shfl_xor_sync(0xffffffffu, m, o));
    if ((tid & 31) == 0) red[tid >> 5] = m;
    __syncthreads();
    float mx = red[0];
#pragma unroll
    for (int i = 1; i < 8; i++) mx = fmaxf(mx, red[i]);
    __syncthreads();

    float s = 0.0f;
#pragma unroll
    for (int e = 0; e < 8; e++) { v[e] = __expf(v[e] - mx); s += v[e]; }
#pragma unroll
    for (int o = 16; o; o >>= 1) s += __shfl_xor_sync(0xffffffffu, s, o);
    if ((tid & 31) == 0) red[tid >> 5] = s;
    __syncthreads();
    float st = 0.0f;
#pragma unroll
    for (int i = 0; i < 8; i++) st += red[i];
    const float inv = 1.0f / st;

    __half hi[8];
#pragma unroll
    for (int e = 0; e < 8; e++) hi[e] = __float2half(v[e] * inv);
    uint4 hv4;
    hv4.x = pk2h(hi[0],hi[1]); hv4.y = pk2h(hi[2],hi[3]);
    hv4.z = pk2h(hi[4],hi[5]); hv4.w = pk2h(hi[6],hi[7]);
    *(uint4*)&Sh[r * 2048 + c0] = hv4;
}

// ---------------------------------------------------------------------------
// Launch — all kernels via PDL (programmatic stream serialization)
// ---------------------------------------------------------------------------
template <typename F, typename... Args>
static inline void launch_pdl(dim3 grid, dim3 block, size_t smem,
                              F func, Args... args)
{
    cudaLaunchConfig_t cfg = {};
    cfg.gridDim = grid;
    cfg.blockDim = block;
    cfg.dynamicSmemBytes = smem;
    cfg.stream = 0;
    cudaLaunchAttribute at[1];
    at[0].id = cudaLaunchAttributeProgrammaticStreamSerialization;
    at[0].val.programmaticStreamSerializationAllowed = 1;
    cfg.attrs = at;
    cfg.numAttrs = 1;
    cudaLaunchKernelEx(&cfg, func, args...);
}

extern "C" void kernel_launch(void* const* d_in, const int* in_sizes, int n_in,
                              void* d_out, int out_size)
{
    const float* X  = (const float*)d_in[0];
    const float* Y  = (const float*)d_in[1];
    const float* Wq = (const float*)d_in[2];
    const float* bq = (const float*)d_in[3];
    const float* Wk = (const float*)d_in[4];
    const float* Wv = (const float*)d_in[6];
    const float* bv = (const float*)d_in[7];
    const float* Wo = (const float*)d_in[8];
    const float* bo = (const float*)d_in[9];
    float* out = (float*)d_out;

    constexpr int SMEM3 = STAGES * (2 * A_TILE_B + 2 * B_TILE_B);   // 184320
    constexpr int SMEM2 = STAGES * (2 * A_TILE_B + 1 * B_TILE_B);   // 122880
    constexpr int SMEM1 = STAGES * (1 * A_TILE_B + 1 * B_TILE_B);   // 92160
    cudaFuncSetAttribute(gemm_mma<3,0,1>, cudaFuncAttributeMaxDynamicSharedMemorySize, SMEM3);
    cudaFuncSetAttribute(gemm_mma<3,1,0>, cudaFuncAttributeMaxDynamicSharedMemorySize, SMEM3);
    cudaFuncSetAttribute(gemm_mma<1,1,0>, cudaFuncAttributeMaxDynamicSharedMemorySize, SMEM1);
    cudaFuncSetAttribute(gemm_mma<2,0,1>, cudaFuncAttributeMaxDynamicSharedMemorySize, SMEM2);

    __half *Xh,*Xl,*Yh,*Yl,*YTh,*Mh,*Ml,*Nh,*Nl,*Th,*Tl,*Ph,*Ch,*Cl;
    float *S,*hv,*wv,*ob;
    cudaGetSymbolAddress((void**)&Xh, g_Xh);   cudaGetSymbolAddress((void**)&Xl, g_Xl);
    cudaGetSymbolAddress((void**)&Yh, g_Yh);   cudaGetSymbolAddress((void**)&Yl, g_Yl);
    cudaGetSymbolAddress((void**)&YTh, g_YTh);
    cudaGetSymbolAddress((void**)&Mh, g_Mh);   cudaGetSymbolAddress((void**)&Ml, g_Ml);
    cudaGetSymbolAddress((void**)&Nh, g_Nh);   cudaGetSymbolAddress((void**)&Nl, g_Nl);
    cudaGetSymbolAddress((void**)&Th, g_Th);   cudaGetSymbolAddress((void**)&Tl, g_Tl);
    cudaGetSymbolAddress((void**)&Ph, g_Ph);
    cudaGetSymbolAddress((void**)&Ch, g_Ch);   cudaGetSymbolAddress((void**)&Cl, g_Cl);
    cudaGetSymbolAddress((void**)&S, g_S);
    cudaGetSymbolAddress((void**)&hv, g_hv);
    cudaGetSymbolAddress((void**)&wv, g_wv);
    cudaGetSymbolAddress((void**)&ob, g_ob);

    // 1: hv (feeds fused wv inside splitY branch)
    launch_pdl(dim3(1), dim3(256), 0, prep_hv, Wk, bq, hv);
    // 2: fused prep
    {
        PrepArgs p{X, Y, Wq, Wk, Wv, Wo, bv, bo, hv,
                   Xh, Xl, Yh, Yl, YTh, Mh, Ml, Nh, Nl,
                   wv, ob};
        launch_pdl(dim3(FP_NBLK), dim3(256), 0, fused_prep, p);
    }
    // 3: T = X @ M -> split [16384,256]   (3-term)
    {
        GemmArgs a{Xh, Xl, Mh, Ml, nullptr, nullptr, Th, Tl,
                   512, 0, 0, 0, 256, 0};
        launch_pdl(dim3(1,128,1), dim3(512), SMEM3, gemm_mma<3,1,0>, a);
    }
    // 4: S = T_z @ Y_z^T + wv -> fp32 [1024,2048] x16   (3-term)
    {
        GemmArgs a{Th, Tl, Yh, Yl, wv, S, nullptr, nullptr,
                   256, (long long)1024*256, (long long)2048*256,
                   (long long)1024*2048, 2048, 2048};
        launch_pdl(dim3(8,8,16), dim3(512), SMEM3, gemm_mma<3,0,1>, a);
    }
    // 5: softmax -> Ph (hi only)
    launch_pdl(dim3(16384), dim3(256), 0, softmax_h, S, Ph);
    // 6: C = Ph @ Yh^T -> split [1024,256] x16   (1-term)
    {
        GemmArgs a{Ph, nullptr, YTh, nullptr, nullptr, nullptr, Ch, Cl,
                   2048, (long long)1024*2048, (long long)256*2048,
                   (long long)1024*256, 256, 0};
        launch_pdl(dim3(1,8,16), dim3(512), SMEM1, gemm_mma<1,1,0>, a);
    }
    // 7: out = (Ch+Cl) @ Nh + ob -> fp32 [16384,512]   (2-term)
    {
        GemmArgs a{Ch, Cl, Nh, nullptr, ob, out, nullptr, nullptr,
                   256, 0, 0, 0, 512, 0};
        launch_pdl(dim3(2,128,1), dim3(512), SMEM2, gemm_mma<2,0,1>, a);
    }
}